// round 1
// baseline (speedup 1.0000x reference)
#include <cuda_runtime.h>
#include <math.h>

#define NTOK   4096          // B*T
#define DMODEL 1024
#define DFF    4096
#define NEXP   8
#define NASSIGN (NTOK*2)

// SCALE = 1/sqrt(N_SHARED + TOP_K/N_EXPERTS) = 1/sqrt(1.25)
#define SCALE_F 0.894427190999915878f

// ---------------- device scratch (static: no runtime allocation) -------------
__device__ float d_Hbuf[(size_t)NASSIGN * DFF];    // up-proj activations (rows reused: shared pass uses 0..4095, routed pass 0..8191)
__device__ float d_ybuf[(size_t)NASSIGN * DMODEL]; // routed expert outputs per assignment row
__device__ float d_gates[NASSIGN];                 // top-2 gate probs per token (slot-ordered)
__device__ int   d_assign_e[NASSIGN];              // expert id per assignment a = 2*t+s
__device__ int   d_counts[NEXP];
__device__ int   d_cursor[NEXP];
__device__ int   d_offsets[NEXP + 1];
__device__ int   d_rows_token[NASSIGN];            // GEMM row r -> token index
__device__ int   d_rowof[NASSIGN];                 // assignment a -> GEMM row r

// ---------------- helpers ----------------------------------------------------
__device__ __forceinline__ float gelu_tanh(float v) {
    // JAX default gelu (approximate=True)
    const float c0 = 0.7978845608028654f;   // sqrt(2/pi)
    const float c1 = 0.044715f;
    float t = tanhf(c0 * (v + c1 * v * v * v));
    return 0.5f * v * (1.0f + t);
}

// ---------------- kernel 0: zero counters ------------------------------------
__global__ void init_kernel() {
    int i = threadIdx.x;
    if (i < NEXP) { d_counts[i] = 0; d_cursor[i] = 0; }
}

// ---------------- kernel 1: router (logits -> softmax -> top-2) --------------
__global__ void router_kernel(const float* __restrict__ x,
                              const float* __restrict__ wr) {
    int t = blockIdx.x;
    int warp = threadIdx.x >> 5;
    int lane = threadIdx.x & 31;
    const float* xr = x + (size_t)t * DMODEL;
    const float* w  = wr + (size_t)warp * DMODEL;
    float s = 0.f;
    #pragma unroll 4
    for (int i = lane; i < DMODEL; i += 32) s += xr[i] * w[i];
    #pragma unroll
    for (int o = 16; o > 0; o >>= 1) s += __shfl_xor_sync(0xFFFFFFFFu, s, o);

    __shared__ float logits[NEXP];
    if (lane == 0) logits[warp] = s;
    __syncthreads();

    if (threadIdx.x == 0) {
        float mx = logits[0];
        #pragma unroll
        for (int e = 1; e < NEXP; e++) mx = fmaxf(mx, logits[e]);
        float p[NEXP]; float sum = 0.f;
        #pragma unroll
        for (int e = 0; e < NEXP; e++) { p[e] = expf(logits[e] - mx); sum += p[e]; }
        float inv = 1.f / sum;
        #pragma unroll
        for (int e = 0; e < NEXP; e++) p[e] *= inv;
        // top-2, ties -> lower index (matches lax.top_k)
        int i0 = 0;
        #pragma unroll
        for (int e = 1; e < NEXP; e++) if (p[e] > p[i0]) i0 = e;
        int i1 = -1;
        #pragma unroll
        for (int e = 0; e < NEXP; e++) {
            if (e == i0) continue;
            if (i1 < 0 || p[e] > p[i1]) i1 = e;
        }
        d_gates[2 * t + 0] = p[i0];
        d_gates[2 * t + 1] = p[i1];
        d_assign_e[2 * t + 0] = i0;
        d_assign_e[2 * t + 1] = i1;
        atomicAdd(&d_counts[i0], 1);
        atomicAdd(&d_counts[i1], 1);
    }
}

// ---------------- kernel 2: exclusive scan over 8 counts ---------------------
__global__ void scan_kernel() {
    if (threadIdx.x == 0) {
        int s = 0;
        for (int e = 0; e < NEXP; e++) { d_offsets[e] = s; s += d_counts[e]; }
        d_offsets[NEXP] = s;
    }
}

// ---------------- kernel 3: place assignments into expert-grouped rows -------
__global__ void place_kernel() {
    int a = blockIdx.x * blockDim.x + threadIdx.x;
    if (a >= NASSIGN) return;
    int e = d_assign_e[a];
    int pos = atomicAdd(&d_cursor[e], 1);
    int r = d_offsets[e] + pos;
    d_rows_token[r] = a >> 1;
    d_rowof[a] = r;
}

// ---------------- GEMM: C[m,n] = act(sum_k A[m,k]*W[n,k] + bias[n]) ----------
// NT layout (both row-major, K contiguous). 128x128 tile, BK=8, 256 thr, 8x8/thr.
// Rows may be gathered (for routed up-proj) and restricted to [lo,hi) per z-slice.
__global__ __launch_bounds__(256, 2)
void gemm_nt(const float* __restrict__ A_base, int lda,
             const int* __restrict__ gather,
             const float* __restrict__ W_base, size_t wstride,
             const float* __restrict__ bias_base, size_t bstride,
             float* __restrict__ C_base, int ldc,
             const int* __restrict__ row_lo_p, const int* __restrict__ row_hi_p,
             int fixedM, int N, int K, int do_gelu)
{
    int e  = blockIdx.z;
    int lo = row_lo_p ? row_lo_p[e] : 0;
    int hi = row_hi_p ? row_hi_p[e] : fixedM;
    int m0 = lo + blockIdx.y * 128;
    if (m0 >= hi) return;
    const float* W    = W_base + (size_t)e * wstride;
    const float* bias = bias_base + (size_t)e * bstride;
    int n0 = blockIdx.x * 128;
    if (n0 >= N) return;

    __shared__ float As[8][128];
    __shared__ float Bs[8][128];

    int tid = threadIdx.x;
    int ar  = tid >> 1;          // 0..127 : row within tile (A) / col within tile (B)
    int ak  = (tid & 1) << 2;    // 0 or 4 : k offset of this thread's float4

    int arow = m0 + ar;
    bool avalid = (arow < hi);
    int  asrc = avalid ? (gather ? gather[arow] : arow) : 0;
    const float* Aptr = A_base + (size_t)asrc * lda;
    const float* Bptr = W + (size_t)(n0 + ar) * K;

    int tm = (tid >> 4) << 3;    // 0..120 step 8
    int tn = (tid & 15) << 3;

    float acc[8][8];
    #pragma unroll
    for (int i = 0; i < 8; i++)
        #pragma unroll
        for (int j = 0; j < 8; j++) acc[i][j] = 0.f;

    for (int k0 = 0; k0 < K; k0 += 8) {
        float4 av = avalid ? *(const float4*)(Aptr + k0 + ak)
                           : make_float4(0.f, 0.f, 0.f, 0.f);
        float4 bv = *(const float4*)(Bptr + k0 + ak);
        __syncthreads();   // previous compute done before smem overwrite
        As[ak + 0][ar] = av.x; As[ak + 1][ar] = av.y;
        As[ak + 2][ar] = av.z; As[ak + 3][ar] = av.w;
        Bs[ak + 0][ar] = bv.x; Bs[ak + 1][ar] = bv.y;
        Bs[ak + 2][ar] = bv.z; Bs[ak + 3][ar] = bv.w;
        __syncthreads();

        #pragma unroll
        for (int k = 0; k < 8; k++) {
            float4 a0 = *(const float4*)&As[k][tm];
            float4 a1 = *(const float4*)&As[k][tm + 4];
            float4 b0 = *(const float4*)&Bs[k][tn];
            float4 b1 = *(const float4*)&Bs[k][tn + 4];
            float a[8] = {a0.x, a0.y, a0.z, a0.w, a1.x, a1.y, a1.z, a1.w};
            float b[8] = {b0.x, b0.y, b0.z, b0.w, b1.x, b1.y, b1.z, b1.w};
            #pragma unroll
            for (int i = 0; i < 8; i++)
                #pragma unroll
                for (int j = 0; j < 8; j++)
                    acc[i][j] = fmaf(a[i], b[j], acc[i][j]);
        }
    }

    // epilogue: bias (+ optional gelu), bounds-checked on M only (N is exact)
    #pragma unroll
    for (int i = 0; i < 8; i++) {
        int row = m0 + tm + i;
        if (row < hi) {
            float* crow = C_base + (size_t)row * ldc + n0 + tn;
            float out[8];
            #pragma unroll
            for (int j = 0; j < 8; j++) {
                float v = acc[i][j] + bias[n0 + tn + j];
                out[j] = do_gelu ? gelu_tanh(v) : v;
            }
            *(float4*)(crow)     = make_float4(out[0], out[1], out[2], out[3]);
            *(float4*)(crow + 4) = make_float4(out[4], out[5], out[6], out[7]);
        }
    }
}

// ---------------- kernel: deterministic combine ------------------------------
__global__ void combine_kernel(float* __restrict__ out) {
    int t = blockIdx.x;
    float g0 = d_gates[2 * t + 0];
    float g1 = d_gates[2 * t + 1];
    const float* y0 = d_ybuf + (size_t)d_rowof[2 * t + 0] * DMODEL;
    const float* y1 = d_ybuf + (size_t)d_rowof[2 * t + 1] * DMODEL;
    float* o = out + (size_t)t * DMODEL;
    for (int d = threadIdx.x * 4; d < DMODEL; d += blockDim.x * 4) {
        float4 ov = *(const float4*)(o + d);
        float4 a  = *(const float4*)(y0 + d);
        float4 b  = *(const float4*)(y1 + d);
        ov.x = SCALE_F * (ov.x + g0 * a.x + g1 * b.x);
        ov.y = SCALE_F * (ov.y + g0 * a.y + g1 * b.y);
        ov.z = SCALE_F * (ov.z + g0 * a.z + g1 * b.z);
        ov.w = SCALE_F * (ov.w + g0 * a.w + g1 * b.w);
        *(float4*)(o + d) = ov;
    }
}

// ---------------- launcher ----------------------------------------------------
extern "C" void kernel_launch(void* const* d_in, const int* in_sizes, int n_in,
                              void* d_out, int out_size)
{
    const float* x   = (const float*)d_in[0];   // [4,1024,1024]
    const float* wr  = (const float*)d_in[1];   // [8,1024]
    const float* W1  = (const float*)d_in[2];   // [8,4096,1024]
    const float* b1  = (const float*)d_in[3];   // [8,4096]
    const float* W2  = (const float*)d_in[4];   // [8,1024,4096]
    const float* b2  = (const float*)d_in[5];   // [8,1024]
    const float* Ws1 = (const float*)d_in[6];   // [4096,1024]
    const float* bs1 = (const float*)d_in[7];   // [4096]
    const float* Ws2 = (const float*)d_in[8];   // [1024,4096]
    const float* bs2 = (const float*)d_in[9];   // [1024]
    float* out = (float*)d_out;

    // device-symbol addresses (looked up every call: no static caching)
    float *Hbuf, *ybuf;
    int *offsets, *rows_token;
    cudaGetSymbolAddress((void**)&Hbuf, d_Hbuf);
    cudaGetSymbolAddress((void**)&ybuf, d_ybuf);
    cudaGetSymbolAddress((void**)&offsets, d_offsets);
    cudaGetSymbolAddress((void**)&rows_token, d_rows_token);

    // 1) routing
    init_kernel<<<1, 32>>>();
    router_kernel<<<NTOK, 256>>>(x, wr);
    scan_kernel<<<1, 32>>>();
    place_kernel<<<(NASSIGN + 255) / 256, 256>>>();

    // 2) shared expert: H = gelu(x @ Ws1^T + bs1) ; out = H @ Ws2^T + bs2
    {
        dim3 g1(DFF / 128, NTOK / 128, 1);
        gemm_nt<<<g1, 256>>>(x, DMODEL, nullptr,
                             Ws1, 0, bs1, 0,
                             Hbuf, DFF,
                             nullptr, nullptr, NTOK, DFF, DMODEL, 1);
        dim3 g2(DMODEL / 128, NTOK / 128, 1);
        gemm_nt<<<g2, 256>>>(Hbuf, DFF, nullptr,
                             Ws2, 0, bs2, 0,
                             out, DMODEL,
                             nullptr, nullptr, NTOK, DMODEL, DFF, 0);
    }

    // 3) routed experts (grouped rows, z = expert)
    {
        dim3 g1(DFF / 128, NTOK / 128, NEXP);   // worst case: one expert owns all tokens
        gemm_nt<<<g1, 256>>>(x, DMODEL, rows_token,
                             W1, (size_t)DFF * DMODEL, b1, (size_t)DFF,
                             Hbuf, DFF,
                             offsets, offsets + 1, 0, DFF, DMODEL, 1);
        dim3 g2(DMODEL / 128, NTOK / 128, NEXP);
        gemm_nt<<<g2, 256>>>(Hbuf, DFF, nullptr,
                             W2, (size_t)DMODEL * DFF, b2, (size_t)DMODEL,
                             ybuf, DMODEL,
                             offsets, offsets + 1, 0, DMODEL, DFF, 0);
    }

    // 4) combine: out = SCALE * (shared + g0*y0 + g1*y1)
    combine_kernel<<<NTOK, 256>>>(out);
}

// round 3
// speedup vs baseline: 2.4135x; 2.4135x over previous
#include <cuda_runtime.h>
#include <cuda_bf16.h>
#include <stdint.h>
#include <math.h>

#define NTOK   4096
#define DMODEL 1024
#define DFF    4096
#define NEXP   8
#define NASSIGN (NTOK*2)
#define SCALE_F 0.894427190999915878f

// ---------------- device scratch ----------------------------------------------
__device__ float d_Hbuf[(size_t)NASSIGN * DFF];
__device__ float d_ybuf[(size_t)NASSIGN * DMODEL];
__device__ float d_gates[NASSIGN];
__device__ int   d_assign_e[NASSIGN];
__device__ int   d_counts[NEXP];
__device__ int   d_cursor[NEXP];
__device__ int   d_offsets[NEXP + 1];
__device__ int   d_rows_token[NASSIGN];
__device__ int   d_rowof[NASSIGN];

// ---------------- helpers ----------------------------------------------------
__device__ __forceinline__ float gelu_tanh(float v) {
    const float c0 = 0.7978845608028654f;
    const float c1 = 0.044715f;
    float t = tanhf(c0 * (v + c1 * v * v * v));
    return 0.5f * v * (1.0f + t);
}

// split one float pair into packed bf16 hi and lo
__device__ __forceinline__ void split2(float x, float y, uint32_t& hi, uint32_t& lo) {
    __nv_bfloat16 hx = __float2bfloat16(x), hy = __float2bfloat16(y);
    float rx = x - __bfloat162float(hx);
    float ry = y - __bfloat162float(hy);
    __nv_bfloat162 hp = __halves2bfloat162(hx, hy);
    __nv_bfloat162 lp = __halves2bfloat162(__float2bfloat16(rx), __float2bfloat16(ry));
    hi = *(uint32_t*)&hp;
    lo = *(uint32_t*)&lp;
}

__device__ __forceinline__ void mma16816(float* c, const uint32_t* a, const uint32_t* b) {
    asm volatile(
        "mma.sync.aligned.m16n8k16.row.col.f32.bf16.bf16.f32 "
        "{%0,%1,%2,%3}, {%4,%5,%6,%7}, {%8,%9}, {%0,%1,%2,%3};"
        : "+f"(c[0]), "+f"(c[1]), "+f"(c[2]), "+f"(c[3])
        : "r"(a[0]), "r"(a[1]), "r"(a[2]), "r"(a[3]), "r"(b[0]), "r"(b[1]));
}

// ---------------- routing kernels ---------------------------------------------
__global__ void init_kernel() {
    int i = threadIdx.x;
    if (i < NEXP) { d_counts[i] = 0; d_cursor[i] = 0; }
}

__global__ void router_kernel(const float* __restrict__ x,
                              const float* __restrict__ wr) {
    int t = blockIdx.x;
    int warp = threadIdx.x >> 5;
    int lane = threadIdx.x & 31;
    const float* xr = x + (size_t)t * DMODEL;
    const float* w  = wr + (size_t)warp * DMODEL;
    float s = 0.f;
    #pragma unroll 4
    for (int i = lane; i < DMODEL; i += 32) s += xr[i] * w[i];
    #pragma unroll
    for (int o = 16; o > 0; o >>= 1) s += __shfl_xor_sync(0xFFFFFFFFu, s, o);

    __shared__ float logits[NEXP];
    if (lane == 0) logits[warp] = s;
    __syncthreads();

    if (threadIdx.x == 0) {
        float mx = logits[0];
        #pragma unroll
        for (int e = 1; e < NEXP; e++) mx = fmaxf(mx, logits[e]);
        float p[NEXP]; float sum = 0.f;
        #pragma unroll
        for (int e = 0; e < NEXP; e++) { p[e] = expf(logits[e] - mx); sum += p[e]; }
        float inv = 1.f / sum;
        #pragma unroll
        for (int e = 0; e < NEXP; e++) p[e] *= inv;
        int i0 = 0;
        #pragma unroll
        for (int e = 1; e < NEXP; e++) if (p[e] > p[i0]) i0 = e;
        int i1 = -1;
        #pragma unroll
        for (int e = 0; e < NEXP; e++) {
            if (e == i0) continue;
            if (i1 < 0 || p[e] > p[i1]) i1 = e;
        }
        d_gates[2 * t + 0] = p[i0];
        d_gates[2 * t + 1] = p[i1];
        d_assign_e[2 * t + 0] = i0;
        d_assign_e[2 * t + 1] = i1;
        atomicAdd(&d_counts[i0], 1);
        atomicAdd(&d_counts[i1], 1);
    }
}

__global__ void scan_kernel() {
    if (threadIdx.x == 0) {
        int s = 0;
        for (int e = 0; e < NEXP; e++) { d_offsets[e] = s; s += d_counts[e]; }
        d_offsets[NEXP] = s;
    }
}

__global__ void place_kernel() {
    int a = blockIdx.x * blockDim.x + threadIdx.x;
    if (a >= NASSIGN) return;
    int e = d_assign_e[a];
    int pos = atomicAdd(&d_cursor[e], 1);
    int r = d_offsets[e] + pos;
    d_rows_token[r] = a >> 1;
    d_rowof[a] = r;
}

// ================= split-bf16 HMMA grouped GEMM ================================
// C[m,n] = act(sum_k A[m,k] * W[n,k] + bias[n]),  fp32 in/out.
// 128x128x32 CTA tile, 256 thr (8 warps 2x4 -> 64x32 warp tiles), m16n8k16 bf16
// mma.sync, 3 passes (AhBh + AhBl + AlBh). Double-buffered smem.
//
// SMEM stage layout (bytes): Ahi @0, Alo @10240, Bhi @20480, Blo @30720
// each tile 128 rows x 40 bf16 (32 data + 8 pad) = 80 B/row (conflict-free frags).
#define RS      80
#define T_ALO   10240
#define T_BHI   20480
#define T_BLO   30720
#define STAGE_B 40960
#define GEMM_SMEM (2 * STAGE_B)

__global__ __launch_bounds__(256, 1)
void gemm_tc(const float* __restrict__ A_base, int lda,
             const int* __restrict__ gather,
             const float* __restrict__ W_base, size_t wstride,
             const float* __restrict__ bias_base, size_t bstride,
             float* __restrict__ C_base, int ldc,
             const int* __restrict__ row_lo_p, const int* __restrict__ row_hi_p,
             int fixedM, int N, int K, int do_gelu)
{
    extern __shared__ char smem[];
    int e  = blockIdx.z;
    int lo = row_lo_p ? row_lo_p[e] : 0;
    int hi = row_hi_p ? row_hi_p[e] : fixedM;
    int m0 = lo + blockIdx.y * 128;
    if (m0 >= hi) return;
    int n0 = blockIdx.x * 128;
    const float* W    = W_base + (size_t)e * wstride;
    const float* bias = bias_base + (size_t)e * bstride;

    int tid  = threadIdx.x;
    int wid  = tid >> 5;
    int lane = tid & 31;
    int g    = lane >> 2;     // 0..7
    int tig  = lane & 3;      // 0..3
    int wm   = wid >> 2;      // 0..1
    int wn   = wid & 3;       // 0..3

    // ---- per-thread global-load coordinates (4 float4 each for A and B) ----
    int ldrow[4], lv[4];            // tile row, A-valid
    const float* aptr[4];
    const float* bptr[4];
    int ldc4[4];
    #pragma unroll
    for (int i = 0; i < 4; i++) {
        int idx = tid + (i << 8);   // 0..1023
        int row = idx >> 3;         // 0..127
        int c4  = (idx & 7) << 2;   // 0,4,...,28
        ldrow[i] = row;
        ldc4[i]  = c4;
        int arow = m0 + row;
        lv[i] = (arow < hi);
        int asrc = lv[i] ? (gather ? gather[arow] : arow) : 0;
        aptr[i] = A_base + (size_t)asrc * lda + c4;
        bptr[i] = W + (size_t)(n0 + row) * K + c4;
    }

    float acc[4][4][4];
    #pragma unroll
    for (int mi = 0; mi < 4; mi++)
        #pragma unroll
        for (int ni = 0; ni < 4; ni++)
            #pragma unroll
            for (int q = 0; q < 4; q++) acc[mi][ni][q] = 0.f;

    int nk = K >> 5;   // K/32
    float4 avr[4], bvr[4];

    // prologue: fetch tile 0
    #pragma unroll
    for (int i = 0; i < 4; i++) {
        avr[i] = lv[i] ? *(const float4*)(aptr[i]) : make_float4(0.f, 0.f, 0.f, 0.f);
        bvr[i] = *(const float4*)(bptr[i]);
    }
    {
        char* st = smem;
        #pragma unroll
        for (int i = 0; i < 4; i++) {
            uint32_t h0, l0, h1, l1;
            int off = ldrow[i] * RS + ldc4[i] * 2;
            split2(avr[i].x, avr[i].y, h0, l0);
            split2(avr[i].z, avr[i].w, h1, l1);
            *(uint2*)(st + off)         = make_uint2(h0, h1);
            *(uint2*)(st + T_ALO + off) = make_uint2(l0, l1);
            split2(bvr[i].x, bvr[i].y, h0, l0);
            split2(bvr[i].z, bvr[i].w, h1, l1);
            *(uint2*)(st + T_BHI + off) = make_uint2(h0, h1);
            *(uint2*)(st + T_BLO + off) = make_uint2(l0, l1);
        }
    }
    __syncthreads();

    for (int kt = 0; kt < nk; kt++) {
        // prefetch next tile into regs
        if (kt + 1 < nk) {
            int kb = (kt + 1) << 5;
            #pragma unroll
            for (int i = 0; i < 4; i++) {
                avr[i] = lv[i] ? *(const float4*)(aptr[i] + kb) : make_float4(0.f, 0.f, 0.f, 0.f);
                bvr[i] = *(const float4*)(bptr[i] + kb);
            }
        }

        // ---- compute on stage kt&1 ----
        char* st = smem + (kt & 1) * STAGE_B;
        #pragma unroll
        for (int ks = 0; ks < 2; ks++) {
            int kbyte = ks * 32 + tig * 4;
            uint32_t ah[4][4], al[4][4];
            #pragma unroll
            for (int mi = 0; mi < 4; mi++) {
                int r0 = (wm * 64 + mi * 16 + g) * RS + kbyte;
                int r1 = r0 + 8 * RS;
                ah[mi][0] = *(const uint32_t*)(st + r0);
                ah[mi][1] = *(const uint32_t*)(st + r1);
                ah[mi][2] = *(const uint32_t*)(st + r0 + 16);
                ah[mi][3] = *(const uint32_t*)(st + r1 + 16);
                al[mi][0] = *(const uint32_t*)(st + T_ALO + r0);
                al[mi][1] = *(const uint32_t*)(st + T_ALO + r1);
                al[mi][2] = *(const uint32_t*)(st + T_ALO + r0 + 16);
                al[mi][3] = *(const uint32_t*)(st + T_ALO + r1 + 16);
            }
            uint32_t bh[4][2], bl[4][2];
            #pragma unroll
            for (int ni = 0; ni < 4; ni++) {
                int rb = (wn * 32 + ni * 8 + g) * RS + kbyte;
                bh[ni][0] = *(const uint32_t*)(st + T_BHI + rb);
                bh[ni][1] = *(const uint32_t*)(st + T_BHI + rb + 16);
                bl[ni][0] = *(const uint32_t*)(st + T_BLO + rb);
                bl[ni][1] = *(const uint32_t*)(st + T_BLO + rb + 16);
            }
            #pragma unroll
            for (int mi = 0; mi < 4; mi++)
                #pragma unroll
                for (int ni = 0; ni < 4; ni++) {
                    mma16816(acc[mi][ni], ah[mi], bh[ni]);
                    mma16816(acc[mi][ni], ah[mi], bl[ni]);
                    mma16816(acc[mi][ni], al[mi], bh[ni]);
                }
        }

        // ---- store prefetched tile to the other stage ----
        if (kt + 1 < nk) {
            char* st2 = smem + ((kt + 1) & 1) * STAGE_B;
            #pragma unroll
            for (int i = 0; i < 4; i++) {
                uint32_t h0, l0, h1, l1;
                int off = ldrow[i] * RS + ldc4[i] * 2;
                split2(avr[i].x, avr[i].y, h0, l0);
                split2(avr[i].z, avr[i].w, h1, l1);
                *(uint2*)(st2 + off)         = make_uint2(h0, h1);
                *(uint2*)(st2 + T_ALO + off) = make_uint2(l0, l1);
                split2(bvr[i].x, bvr[i].y, h0, l0);
                split2(bvr[i].z, bvr[i].w, h1, l1);
                *(uint2*)(st2 + T_BHI + off) = make_uint2(h0, h1);
                *(uint2*)(st2 + T_BLO + off) = make_uint2(l0, l1);
            }
            __syncthreads();
        }
    }

    // ---------------- epilogue: bias (+gelu) + direct STG -----------------------
    #pragma unroll
    for (int mi = 0; mi < 4; mi++) {
        int row0 = m0 + wm * 64 + mi * 16 + g;
        int row1 = row0 + 8;
        #pragma unroll
        for (int ni = 0; ni < 4; ni++) {
            int cn = n0 + wn * 32 + ni * 8 + tig * 2;
            float b0 = bias[cn], b1 = bias[cn + 1];
            if (row0 < hi) {
                float v0 = acc[mi][ni][0] + b0;
                float v1 = acc[mi][ni][1] + b1;
                if (do_gelu) { v0 = gelu_tanh(v0); v1 = gelu_tanh(v1); }
                *(float2*)(C_base + (size_t)row0 * ldc + cn) = make_float2(v0, v1);
            }
            if (row1 < hi) {
                float v0 = acc[mi][ni][2] + b0;
                float v1 = acc[mi][ni][3] + b1;
                if (do_gelu) { v0 = gelu_tanh(v0); v1 = gelu_tanh(v1); }
                *(float2*)(C_base + (size_t)row1 * ldc + cn) = make_float2(v0, v1);
            }
        }
    }
}

// ---------------- combine ------------------------------------------------------
__global__ void combine_kernel(float* __restrict__ out) {
    int t = blockIdx.x;
    float g0 = d_gates[2 * t + 0];
    float g1 = d_gates[2 * t + 1];
    const float* y0 = d_ybuf + (size_t)d_rowof[2 * t + 0] * DMODEL;
    const float* y1 = d_ybuf + (size_t)d_rowof[2 * t + 1] * DMODEL;
    float* o = out + (size_t)t * DMODEL;
    for (int d = threadIdx.x * 4; d < DMODEL; d += blockDim.x * 4) {
        float4 ov = *(const float4*)(o + d);
        float4 a  = *(const float4*)(y0 + d);
        float4 b  = *(const float4*)(y1 + d);
        ov.x = SCALE_F * (ov.x + g0 * a.x + g1 * b.x);
        ov.y = SCALE_F * (ov.y + g0 * a.y + g1 * b.y);
        ov.z = SCALE_F * (ov.z + g0 * a.z + g1 * b.z);
        ov.w = SCALE_F * (ov.w + g0 * a.w + g1 * b.w);
        *(float4*)(o + d) = ov;
    }
}

// ---------------- launcher ------------------------------------------------------
extern "C" void kernel_launch(void* const* d_in, const int* in_sizes, int n_in,
                              void* d_out, int out_size)
{
    const float* x   = (const float*)d_in[0];
    const float* wr  = (const float*)d_in[1];
    const float* W1  = (const float*)d_in[2];
    const float* b1  = (const float*)d_in[3];
    const float* W2  = (const float*)d_in[4];
    const float* b2  = (const float*)d_in[5];
    const float* Ws1 = (const float*)d_in[6];
    const float* bs1 = (const float*)d_in[7];
    const float* Ws2 = (const float*)d_in[8];
    const float* bs2 = (const float*)d_in[9];
    float* out = (float*)d_out;

    float *Hbuf, *ybuf;
    int *offsets, *rows_token;
    cudaGetSymbolAddress((void**)&Hbuf, d_Hbuf);
    cudaGetSymbolAddress((void**)&ybuf, d_ybuf);
    cudaGetSymbolAddress((void**)&offsets, d_offsets);
    cudaGetSymbolAddress((void**)&rows_token, d_rows_token);

    cudaFuncSetAttribute(gemm_tc, cudaFuncAttributeMaxDynamicSharedMemorySize, GEMM_SMEM);

    // 1) routing
    init_kernel<<<1, 32>>>();
    router_kernel<<<NTOK, 256>>>(x, wr);
    scan_kernel<<<1, 32>>>();
    place_kernel<<<(NASSIGN + 255) / 256, 256>>>();

    // 2) shared expert
    {
        dim3 g1(DFF / 128, NTOK / 128, 1);
        gemm_tc<<<g1, 256, GEMM_SMEM>>>(x, DMODEL, nullptr,
                                        Ws1, 0, bs1, 0,
                                        Hbuf, DFF,
                                        nullptr, nullptr, NTOK, DFF, DMODEL, 1);
        dim3 g2(DMODEL / 128, NTOK / 128, 1);
        gemm_tc<<<g2, 256, GEMM_SMEM>>>(Hbuf, DFF, nullptr,
                                        Ws2, 0, bs2, 0,
                                        out, DMODEL,
                                        nullptr, nullptr, NTOK, DMODEL, DFF, 0);
    }

    // 3) routed experts
    {
        dim3 g1(DFF / 128, NASSIGN / 128, NEXP);
        gemm_tc<<<g1, 256, GEMM_SMEM>>>(x, DMODEL, rows_token,
                                        W1, (size_t)DFF * DMODEL, b1, (size_t)DFF,
                                        Hbuf, DFF,
                                        offsets, offsets + 1, 0, DFF, DMODEL, 1);
        dim3 g2(DMODEL / 128, NASSIGN / 128, NEXP);
        gemm_tc<<<g2, 256, GEMM_SMEM>>>(Hbuf, DFF, nullptr,
                                        W2, (size_t)DMODEL * DFF, b2, (size_t)DMODEL,
                                        ybuf, DMODEL,
                                        offsets, offsets + 1, 0, DMODEL, DFF, 0);
    }

    // 4) combine
    combine_kernel<<<NTOK, 256>>>(out);
}

// round 4
// speedup vs baseline: 2.4319x; 1.0076x over previous
#include <cuda_runtime.h>
#include <cuda_bf16.h>
#include <stdint.h>
#include <math.h>

#define NTOK   4096
#define DMODEL 1024
#define DFF    4096
#define NEXP   8
#define NASSIGN (NTOK*2)
#define SCALE_F 0.894427190999915878f

// ---------------- device scratch (bf16 hi/lo planes + fp32 y) -------------------
__device__ __nv_bfloat16 d_W1h[(size_t)NEXP * DFF * DMODEL];
__device__ __nv_bfloat16 d_W1l[(size_t)NEXP * DFF * DMODEL];
__device__ __nv_bfloat16 d_W2h[(size_t)NEXP * DMODEL * DFF];
__device__ __nv_bfloat16 d_W2l[(size_t)NEXP * DMODEL * DFF];
__device__ __nv_bfloat16 d_Ws1h[(size_t)DFF * DMODEL];
__device__ __nv_bfloat16 d_Ws1l[(size_t)DFF * DMODEL];
__device__ __nv_bfloat16 d_Ws2h[(size_t)DMODEL * DFF];
__device__ __nv_bfloat16 d_Ws2l[(size_t)DMODEL * DFF];
__device__ __nv_bfloat16 d_xh[(size_t)NTOK * DMODEL];
__device__ __nv_bfloat16 d_xl[(size_t)NTOK * DMODEL];
__device__ __nv_bfloat16 d_Hh[(size_t)NASSIGN * DFF];
__device__ __nv_bfloat16 d_Hl[(size_t)NASSIGN * DFF];
__device__ float d_ybuf[(size_t)NASSIGN * DMODEL];
__device__ float d_gates[NASSIGN];
__device__ int   d_assign_e[NASSIGN];
__device__ int   d_counts[NEXP];
__device__ int   d_cursor[NEXP];
__device__ int   d_offsets[NEXP + 1];
__device__ int   d_rows_token[NASSIGN];
__device__ int   d_rowof[NASSIGN];

// ---------------- helpers --------------------------------------------------------
__device__ __forceinline__ float gelu_tanh(float v) {
    const float c0 = 0.7978845608028654f;
    const float c1 = 0.044715f;
    float t = tanhf(c0 * (v + c1 * v * v * v));
    return 0.5f * v * (1.0f + t);
}

__device__ __forceinline__ void split2(float x, float y, uint32_t& hi, uint32_t& lo) {
    __nv_bfloat16 hx = __float2bfloat16(x), hy = __float2bfloat16(y);
    float rx = x - __bfloat162float(hx);
    float ry = y - __bfloat162float(hy);
    __nv_bfloat162 hp = __halves2bfloat162(hx, hy);
    __nv_bfloat162 lp = __halves2bfloat162(__float2bfloat16(rx), __float2bfloat16(ry));
    hi = *(uint32_t*)&hp;
    lo = *(uint32_t*)&lp;
}

__device__ __forceinline__ void mma16816(float* c, const uint32_t* a, const uint32_t* b) {
    asm volatile(
        "mma.sync.aligned.m16n8k16.row.col.f32.bf16.bf16.f32 "
        "{%0,%1,%2,%3}, {%4,%5,%6,%7}, {%8,%9}, {%0,%1,%2,%3};"
        : "+f"(c[0]), "+f"(c[1]), "+f"(c[2]), "+f"(c[3])
        : "r"(a[0]), "r"(a[1]), "r"(a[2]), "r"(a[3]), "r"(b[0]), "r"(b[1]));
}

__device__ __forceinline__ void ldsm4(uint32_t* r, uint32_t addr) {
    asm volatile("ldmatrix.sync.aligned.m8n8.x4.shared.b16 {%0,%1,%2,%3}, [%4];"
                 : "=r"(r[0]), "=r"(r[1]), "=r"(r[2]), "=r"(r[3]) : "r"(addr));
}

__device__ __forceinline__ uint32_t smem_u32(const void* p) {
    uint32_t a;
    asm("{ .reg .u64 t; cvta.to.shared.u64 t, %1; cvt.u32.u64 %0, t; }" : "=r"(a) : "l"(p));
    return a;
}

// ---------------- split fp32 -> bf16 hi/lo planes --------------------------------
__global__ void split_kernel(const float4* __restrict__ src,
                             uint2* __restrict__ hi, uint2* __restrict__ lo, int n4) {
    for (int i = blockIdx.x * blockDim.x + threadIdx.x; i < n4; i += gridDim.x * blockDim.x) {
        float4 v = src[i];
        uint32_t h0, l0, h1, l1;
        split2(v.x, v.y, h0, l0);
        split2(v.z, v.w, h1, l1);
        hi[i] = make_uint2(h0, h1);
        lo[i] = make_uint2(l0, l1);
    }
}

// ---------------- routing kernels -------------------------------------------------
__global__ void init_kernel() {
    int i = threadIdx.x;
    if (i < NEXP) { d_counts[i] = 0; d_cursor[i] = 0; }
}

__global__ void router_kernel(const float* __restrict__ x,
                              const float* __restrict__ wr) {
    int t = blockIdx.x;
    int warp = threadIdx.x >> 5;
    int lane = threadIdx.x & 31;
    const float* xr = x + (size_t)t * DMODEL;
    const float* w  = wr + (size_t)warp * DMODEL;
    float s = 0.f;
    #pragma unroll 4
    for (int i = lane; i < DMODEL; i += 32) s += xr[i] * w[i];
    #pragma unroll
    for (int o = 16; o > 0; o >>= 1) s += __shfl_xor_sync(0xFFFFFFFFu, s, o);

    __shared__ float logits[NEXP];
    if (lane == 0) logits[warp] = s;
    __syncthreads();

    if (threadIdx.x == 0) {
        float mx = logits[0];
        #pragma unroll
        for (int e = 1; e < NEXP; e++) mx = fmaxf(mx, logits[e]);
        float p[NEXP]; float sum = 0.f;
        #pragma unroll
        for (int e = 0; e < NEXP; e++) { p[e] = expf(logits[e] - mx); sum += p[e]; }
        float inv = 1.f / sum;
        #pragma unroll
        for (int e = 0; e < NEXP; e++) p[e] *= inv;
        int i0 = 0;
        #pragma unroll
        for (int e = 1; e < NEXP; e++) if (p[e] > p[i0]) i0 = e;
        int i1 = -1;
        #pragma unroll
        for (int e = 0; e < NEXP; e++) {
            if (e == i0) continue;
            if (i1 < 0 || p[e] > p[i1]) i1 = e;
        }
        d_gates[2 * t + 0] = p[i0];
        d_gates[2 * t + 1] = p[i1];
        d_assign_e[2 * t + 0] = i0;
        d_assign_e[2 * t + 1] = i1;
        atomicAdd(&d_counts[i0], 1);
        atomicAdd(&d_counts[i1], 1);
    }
}

__global__ void scan_kernel() {
    if (threadIdx.x == 0) {
        int s = 0;
        for (int e = 0; e < NEXP; e++) { d_offsets[e] = s; s += d_counts[e]; }
        d_offsets[NEXP] = s;
    }
}

__global__ void place_kernel() {
    int a = blockIdx.x * blockDim.x + threadIdx.x;
    if (a >= NASSIGN) return;
    int e = d_assign_e[a];
    int pos = atomicAdd(&d_cursor[e], 1);
    int r = d_offsets[e] + pos;
    d_rows_token[r] = a >> 1;
    d_rowof[a] = r;
}

// ================= split-bf16 HMMA grouped GEMM (ldmatrix, pass-major) ===========
// C = act(A*W^T + bias). A,B given as bf16 hi/lo planes ([rows][K], K contiguous).
// 128x128x32 CTA tile, 256 thr (8 warps 2x4), m16n8k16, 3 passes.
// SMEM stage: Ahi@0, Alo@10240, Bhi@20480, Blo@30720; 80 B/row (64 data + 16 pad).
#define RS      80
#define T_ALO   10240
#define T_BHI   20480
#define T_BLO   30720
#define STAGE_B 40960
#define GEMM_SMEM (2 * STAGE_B)

__global__ __launch_bounds__(256, 1)
void gemm_tc(const __nv_bfloat16* __restrict__ Ahi, const __nv_bfloat16* __restrict__ Alo,
             int lda, const int* __restrict__ gather,
             const __nv_bfloat16* __restrict__ Bh_base, const __nv_bfloat16* __restrict__ Bl_base,
             size_t wstride,
             const float* __restrict__ bias_base, size_t bstride,
             float* __restrict__ Cf, __nv_bfloat16* __restrict__ Chi, __nv_bfloat16* __restrict__ Clo,
             int ldc,
             const int* __restrict__ row_lo_p, const int* __restrict__ row_hi_p,
             int fixedM, int K, int do_gelu)
{
    extern __shared__ char smem[];
    int e  = blockIdx.z;
    int lo = row_lo_p ? row_lo_p[e] : 0;
    int hi = row_hi_p ? row_hi_p[e] : fixedM;
    int m0 = lo + blockIdx.y * 128;
    if (m0 >= hi) return;
    int n0 = blockIdx.x * 128;
    const __nv_bfloat16* Bh = Bh_base + (size_t)e * wstride;
    const __nv_bfloat16* Bl = Bl_base + (size_t)e * wstride;
    const float* bias = bias_base + (size_t)e * bstride;

    uint32_t sbase = smem_u32(smem);
    int tid  = threadIdx.x;
    int wid  = tid >> 5;
    int lane = tid & 31;
    int tig  = lane & 3;
    int wm   = wid >> 2;      // 0..1
    int wn   = wid & 3;       // 0..3

    // ---- global-load coordinates: 2 row-slots per thread, 16B chunk each --------
    int rA[2]; rA[0] = tid >> 2; rA[1] = (tid >> 2) + 64;
    int ch = tid & 3;
    const __nv_bfloat16 *pAh[2], *pAl[2], *pBh[2], *pBl[2];
    int avalid[2];
    uint32_t soff[2];
    #pragma unroll
    for (int j = 0; j < 2; j++) {
        int arow = m0 + rA[j];
        avalid[j] = (arow < hi);
        int asrc = avalid[j] ? (gather ? gather[arow] : arow) : 0;
        pAh[j] = Ahi + (size_t)asrc * lda + ch * 8;
        pAl[j] = Alo + (size_t)asrc * lda + ch * 8;
        pBh[j] = Bh + (size_t)(n0 + rA[j]) * K + ch * 8;
        pBl[j] = Bl + (size_t)(n0 + rA[j]) * K + ch * 8;
        soff[j] = (uint32_t)(rA[j] * RS + ch * 16);
    }

    // ---- ldmatrix lane offsets ----------------------------------------------------
    uint32_t aoff[4], boff[4];
    #pragma unroll
    for (int mi = 0; mi < 4; mi++)
        aoff[mi] = (uint32_t)((wm * 64 + mi * 16 + (lane & 15)) * RS + (lane >> 4) * 16);
    #pragma unroll
    for (int ni = 0; ni < 4; ni++)
        boff[ni] = (uint32_t)((wn * 32 + ni * 8 + (lane & 7)) * RS + (lane >> 3) * 16);

    float acc[4][4][4];
    #pragma unroll
    for (int mi = 0; mi < 4; mi++)
        #pragma unroll
        for (int ni = 0; ni < 4; ni++)
            #pragma unroll
            for (int q = 0; q < 4; q++) acc[mi][ni][q] = 0.f;

    int nk = K >> 5;
    uint4 vAh[2], vAl[2], vBh[2], vBl[2];
    const uint4 z4 = make_uint4(0u, 0u, 0u, 0u);

    // prologue: tile 0 -> stage 0
    #pragma unroll
    for (int j = 0; j < 2; j++) {
        vAh[j] = avalid[j] ? *(const uint4*)(pAh[j]) : z4;
        vAl[j] = avalid[j] ? *(const uint4*)(pAl[j]) : z4;
        vBh[j] = *(const uint4*)(pBh[j]);
        vBl[j] = *(const uint4*)(pBl[j]);
    }
    #pragma unroll
    for (int j = 0; j < 2; j++) {
        *(uint4*)(smem + soff[j])          = vAh[j];
        *(uint4*)(smem + T_ALO + soff[j])  = vAl[j];
        *(uint4*)(smem + T_BHI + soff[j])  = vBh[j];
        *(uint4*)(smem + T_BLO + soff[j])  = vBl[j];
    }
    __syncthreads();

    for (int kt = 0; kt < nk; kt++) {
        if (kt + 1 < nk) {
            int kb = (kt + 1) << 5;
            #pragma unroll
            for (int j = 0; j < 2; j++) {
                vAh[j] = avalid[j] ? *(const uint4*)(pAh[j] + kb) : z4;
                vAl[j] = avalid[j] ? *(const uint4*)(pAl[j] + kb) : z4;
                vBh[j] = *(const uint4*)(pBh[j] + kb);
                vBl[j] = *(const uint4*)(pBl[j] + kb);
            }
        }

        uint32_t st = sbase + (uint32_t)((kt & 1) * STAGE_B);

        // B fragments for full kt (both k-halves)
        uint32_t bhf[4][4], blf[4][4];
        #pragma unroll
        for (int ni = 0; ni < 4; ni++) {
            ldsm4(bhf[ni], st + T_BHI + boff[ni]);
            ldsm4(blf[ni], st + T_BLO + boff[ni]);
        }

        #pragma unroll
        for (int ks = 0; ks < 2; ks++) {
            uint32_t ahf[4][4], alf[4][4];
            #pragma unroll
            for (int mi = 0; mi < 4; mi++) {
                ldsm4(ahf[mi], st + aoff[mi] + ks * 32);
                ldsm4(alf[mi], st + T_ALO + aoff[mi] + ks * 32);
            }
            // pass-major: 16 independent accumulators between reuses
            #pragma unroll
            for (int mi = 0; mi < 4; mi++)
                #pragma unroll
                for (int ni = 0; ni < 4; ni++)
                    mma16816(acc[mi][ni], ahf[mi], &bhf[ni][2 * ks]);
            #pragma unroll
            for (int mi = 0; mi < 4; mi++)
                #pragma unroll
                for (int ni = 0; ni < 4; ni++)
                    mma16816(acc[mi][ni], ahf[mi], &blf[ni][2 * ks]);
            #pragma unroll
            for (int mi = 0; mi < 4; mi++)
                #pragma unroll
                for (int ni = 0; ni < 4; ni++)
                    mma16816(acc[mi][ni], alf[mi], &bhf[ni][2 * ks]);
        }

        if (kt + 1 < nk) {
            char* s2 = smem + ((kt + 1) & 1) * STAGE_B;
            #pragma unroll
            for (int j = 0; j < 2; j++) {
                *(uint4*)(s2 + soff[j])         = vAh[j];
                *(uint4*)(s2 + T_ALO + soff[j]) = vAl[j];
                *(uint4*)(s2 + T_BHI + soff[j]) = vBh[j];
                *(uint4*)(s2 + T_BLO + soff[j]) = vBl[j];
            }
            __syncthreads();
        }
    }

    // ---------------- epilogue ------------------------------------------------------
    int g = lane >> 2;
    #pragma unroll
    for (int mi = 0; mi < 4; mi++) {
        int row0 = m0 + wm * 64 + mi * 16 + g;
        int row1 = row0 + 8;
        #pragma unroll
        for (int ni = 0; ni < 4; ni++) {
            int cn = n0 + wn * 32 + ni * 8 + tig * 2;
            float b0 = bias[cn], b1 = bias[cn + 1];
            #pragma unroll
            for (int h = 0; h < 2; h++) {
                int row = h ? row1 : row0;
                if (row >= hi) continue;
                float v0 = acc[mi][ni][2 * h + 0] + b0;
                float v1 = acc[mi][ni][2 * h + 1] + b1;
                if (do_gelu) { v0 = gelu_tanh(v0); v1 = gelu_tanh(v1); }
                if (Chi) {
                    uint32_t hp, lp;
                    split2(v0, v1, hp, lp);
                    *(uint32_t*)(Chi + (size_t)row * ldc + cn) = hp;
                    *(uint32_t*)(Clo + (size_t)row * ldc + cn) = lp;
                } else {
                    *(float2*)(Cf + (size_t)row * ldc + cn) = make_float2(v0, v1);
                }
            }
        }
    }
}

// ---------------- combine ----------------------------------------------------------
__global__ void combine_kernel(float* __restrict__ out) {
    int t = blockIdx.x;
    float g0 = d_gates[2 * t + 0];
    float g1 = d_gates[2 * t + 1];
    const float* y0 = d_ybuf + (size_t)d_rowof[2 * t + 0] * DMODEL;
    const float* y1 = d_ybuf + (size_t)d_rowof[2 * t + 1] * DMODEL;
    float* o = out + (size_t)t * DMODEL;
    for (int d = threadIdx.x * 4; d < DMODEL; d += blockDim.x * 4) {
        float4 ov = *(const float4*)(o + d);
        float4 a  = *(const float4*)(y0 + d);
        float4 b  = *(const float4*)(y1 + d);
        ov.x = SCALE_F * (ov.x + g0 * a.x + g1 * b.x);
        ov.y = SCALE_F * (ov.y + g0 * a.y + g1 * b.y);
        ov.z = SCALE_F * (ov.z + g0 * a.z + g1 * b.z);
        ov.w = SCALE_F * (ov.w + g0 * a.w + g1 * b.w);
        *(float4*)(o + d) = ov;
    }
}

// ---------------- launcher -----------------------------------------------------------
extern "C" void kernel_launch(void* const* d_in, const int* in_sizes, int n_in,
                              void* d_out, int out_size)
{
    const float* x   = (const float*)d_in[0];
    const float* wr  = (const float*)d_in[1];
    const float* W1  = (const float*)d_in[2];
    const float* b1  = (const float*)d_in[3];
    const float* W2  = (const float*)d_in[4];
    const float* b2  = (const float*)d_in[5];
    const float* Ws1 = (const float*)d_in[6];
    const float* bs1 = (const float*)d_in[7];
    const float* Ws2 = (const float*)d_in[8];
    const float* bs2 = (const float*)d_in[9];
    float* out = (float*)d_out;

    __nv_bfloat16 *W1h, *W1l, *W2h, *W2l, *Ws1h, *Ws1l, *Ws2h, *Ws2l, *xh, *xl, *Hh, *Hl;
    float *ybuf;
    int *offsets, *rows_token;
    cudaGetSymbolAddress((void**)&W1h, d_W1h);   cudaGetSymbolAddress((void**)&W1l, d_W1l);
    cudaGetSymbolAddress((void**)&W2h, d_W2h);   cudaGetSymbolAddress((void**)&W2l, d_W2l);
    cudaGetSymbolAddress((void**)&Ws1h, d_Ws1h); cudaGetSymbolAddress((void**)&Ws1l, d_Ws1l);
    cudaGetSymbolAddress((void**)&Ws2h, d_Ws2h); cudaGetSymbolAddress((void**)&Ws2l, d_Ws2l);
    cudaGetSymbolAddress((void**)&xh, d_xh);     cudaGetSymbolAddress((void**)&xl, d_xl);
    cudaGetSymbolAddress((void**)&Hh, d_Hh);     cudaGetSymbolAddress((void**)&Hl, d_Hl);
    cudaGetSymbolAddress((void**)&ybuf, d_ybuf);
    cudaGetSymbolAddress((void**)&offsets, d_offsets);
    cudaGetSymbolAddress((void**)&rows_token, d_rows_token);

    cudaFuncSetAttribute(gemm_tc, cudaFuncAttributeMaxDynamicSharedMemorySize, GEMM_SMEM);

    // 1) routing + splits
    init_kernel<<<1, 32>>>();
    router_kernel<<<NTOK, 256>>>(x, wr);
    scan_kernel<<<1, 32>>>();
    place_kernel<<<(NASSIGN + 255) / 256, 256>>>();

    split_kernel<<<4096, 256>>>((const float4*)x,   (uint2*)xh,   (uint2*)xl,   NTOK * DMODEL / 4);
    split_kernel<<<8192, 256>>>((const float4*)W1,  (uint2*)W1h,  (uint2*)W1l,  NEXP * DFF * DMODEL / 4);
    split_kernel<<<8192, 256>>>((const float4*)W2,  (uint2*)W2h,  (uint2*)W2l,  NEXP * DMODEL * DFF / 4);
    split_kernel<<<4096, 256>>>((const float4*)Ws1, (uint2*)Ws1h, (uint2*)Ws1l, DFF * DMODEL / 4);
    split_kernel<<<4096, 256>>>((const float4*)Ws2, (uint2*)Ws2h, (uint2*)Ws2l, DMODEL * DFF / 4);

    // 2) shared expert: H(bf16 hi/lo) = gelu(x Ws1^T + bs1); out = H Ws2^T + bs2
    {
        dim3 g1(DFF / 128, NTOK / 128, 1);
        gemm_tc<<<g1, 256, GEMM_SMEM>>>(xh, xl, DMODEL, nullptr,
                                        Ws1h, Ws1l, 0, bs1, 0,
                                        nullptr, Hh, Hl, DFF,
                                        nullptr, nullptr, NTOK, DMODEL, 1);
        dim3 g2(DMODEL / 128, NTOK / 128, 1);
        gemm_tc<<<g2, 256, GEMM_SMEM>>>(Hh, Hl, DFF, nullptr,
                                        Ws2h, Ws2l, 0, bs2, 0,
                                        out, nullptr, nullptr, DMODEL,
                                        nullptr, nullptr, NTOK, DFF, 0);
    }

    // 3) routed experts (H rows reused after shared down-proj consumed them)
    {
        dim3 g1(DFF / 128, NASSIGN / 128, NEXP);
        gemm_tc<<<g1, 256, GEMM_SMEM>>>(xh, xl, DMODEL, rows_token,
                                        W1h, W1l, (size_t)DFF * DMODEL, b1, (size_t)DFF,
                                        nullptr, Hh, Hl, DFF,
                                        offsets, offsets + 1, 0, DMODEL, 1);
        dim3 g2(DMODEL / 128, NASSIGN / 128, NEXP);
        gemm_tc<<<g2, 256, GEMM_SMEM>>>(Hh, Hl, DFF, nullptr,
                                        W2h, W2l, (size_t)DMODEL * DFF, b2, (size_t)DMODEL,
                                        ybuf, nullptr, nullptr, DMODEL,
                                        offsets, offsets + 1, 0, DFF, 0);
    }

    // 4) combine
    combine_kernel<<<NTOK, 256>>>(out);
}

// round 6
// speedup vs baseline: 2.8601x; 1.1761x over previous
#include <cuda_runtime.h>
#include <cuda_fp16.h>
#include <stdint.h>
#include <math.h>

#define NTOK   4096
#define DMODEL 1024
#define DFF    4096
#define NEXP   8
#define NASSIGN (NTOK*2)
#define SCALE_F 0.894427190999915878f

// ---------------- device scratch (fp16 planes) ----------------------------------
__device__ __half d_W1h[(size_t)NEXP * DFF * DMODEL];   // weights: single fp16 plane
__device__ __half d_W2h[(size_t)NEXP * DMODEL * DFF];
__device__ __half d_Ws1h[(size_t)DFF * DMODEL];
__device__ __half d_Ws2h[(size_t)DMODEL * DFF];
__device__ __half d_xh[(size_t)NTOK * DMODEL];          // activations: hi/lo planes
__device__ __half d_xl[(size_t)NTOK * DMODEL];
__device__ __half d_Hh[(size_t)NASSIGN * DFF];
__device__ __half d_Hl[(size_t)NASSIGN * DFF];
__device__ float d_ybuf[(size_t)NASSIGN * DMODEL];
__device__ float d_gates[NASSIGN];
__device__ int   d_assign_e[NASSIGN];
__device__ int   d_counts[NEXP];
__device__ int   d_cursor[NEXP];
__device__ int   d_offsets[NEXP + 1];
__device__ int   d_rows_token[NASSIGN];
__device__ int   d_rowof[NASSIGN];

// ---------------- helpers --------------------------------------------------------
__device__ __forceinline__ float gelu_tanh(float v) {
    const float c0 = 0.7978845608028654f;
    const float c1 = 0.044715f;
    float t = tanhf(c0 * (v + c1 * v * v * v));
    return 0.5f * v * (1.0f + t);
}

// split one float pair into packed fp16 hi and lo
__device__ __forceinline__ void split2h(float x, float y, uint32_t& hi, uint32_t& lo) {
    __half hx = __float2half_rn(x), hy = __float2half_rn(y);
    float rx = x - __half2float(hx);
    float ry = y - __half2float(hy);
    __half2 hp = __halves2half2(hx, hy);
    __half2 lp = __halves2half2(__float2half_rn(rx), __float2half_rn(ry));
    hi = *(uint32_t*)&hp;
    lo = *(uint32_t*)&lp;
}

__device__ __forceinline__ void mma16816(float* c, const uint32_t* a, const uint32_t* b) {
    asm volatile(
        "mma.sync.aligned.m16n8k16.row.col.f32.f16.f16.f32 "
        "{%0,%1,%2,%3}, {%4,%5,%6,%7}, {%8,%9}, {%0,%1,%2,%3};"
        : "+f"(c[0]), "+f"(c[1]), "+f"(c[2]), "+f"(c[3])
        : "r"(a[0]), "r"(a[1]), "r"(a[2]), "r"(a[3]), "r"(b[0]), "r"(b[1]));
}

__device__ __forceinline__ void ldsm4(uint32_t* r, uint32_t addr) {
    asm volatile("ldmatrix.sync.aligned.m8n8.x4.shared.b16 {%0,%1,%2,%3}, [%4];"
                 : "=r"(r[0]), "=r"(r[1]), "=r"(r[2]), "=r"(r[3]) : "r"(addr));
}

__device__ __forceinline__ uint32_t smem_u32(const void* p) {
    uint32_t a;
    asm("{ .reg .u64 t; cvta.to.shared.u64 t, %1; cvt.u32.u64 %0, t; }" : "=r"(a) : "l"(p));
    return a;
}

// ---------------- conversion kernels ----------------------------------------------
__global__ void cvt_f16(const float4* __restrict__ src, uint2* __restrict__ dst, int n4) {
    for (int i = blockIdx.x * blockDim.x + threadIdx.x; i < n4; i += gridDim.x * blockDim.x) {
        float4 v = src[i];
        __half2 a = __floats2half2_rn(v.x, v.y);
        __half2 b = __floats2half2_rn(v.z, v.w);
        dst[i] = make_uint2(*(uint32_t*)&a, *(uint32_t*)&b);
    }
}
__global__ void split_f16(const float4* __restrict__ src,
                          uint2* __restrict__ hi, uint2* __restrict__ lo, int n4) {
    for (int i = blockIdx.x * blockDim.x + threadIdx.x; i < n4; i += gridDim.x * blockDim.x) {
        float4 v = src[i];
        uint32_t h0, l0, h1, l1;
        split2h(v.x, v.y, h0, l0);
        split2h(v.z, v.w, h1, l1);
        hi[i] = make_uint2(h0, h1);
        lo[i] = make_uint2(l0, l1);
    }
}

// ---------------- routing kernels ---------------------------------------------------
__global__ void init_kernel() {
    int i = threadIdx.x;
    if (i < NEXP) { d_counts[i] = 0; d_cursor[i] = 0; }
}

__global__ void router_kernel(const float* __restrict__ x,
                              const float* __restrict__ wr) {
    int t = blockIdx.x;
    int warp = threadIdx.x >> 5;
    int lane = threadIdx.x & 31;
    const float* xr = x + (size_t)t * DMODEL;
    const float* w  = wr + (size_t)warp * DMODEL;
    float s = 0.f;
    #pragma unroll 4
    for (int i = lane; i < DMODEL; i += 32) s += xr[i] * w[i];
    #pragma unroll
    for (int o = 16; o > 0; o >>= 1) s += __shfl_xor_sync(0xFFFFFFFFu, s, o);

    __shared__ float logits[NEXP];
    if (lane == 0) logits[warp] = s;
    __syncthreads();

    if (threadIdx.x == 0) {
        float mx = logits[0];
        #pragma unroll
        for (int e = 1; e < NEXP; e++) mx = fmaxf(mx, logits[e]);
        float p[NEXP]; float sum = 0.f;
        #pragma unroll
        for (int e = 0; e < NEXP; e++) { p[e] = expf(logits[e] - mx); sum += p[e]; }
        float inv = 1.f / sum;
        #pragma unroll
        for (int e = 0; e < NEXP; e++) p[e] *= inv;
        int i0 = 0;
        #pragma unroll
        for (int e = 1; e < NEXP; e++) if (p[e] > p[i0]) i0 = e;
        int i1 = -1;
        #pragma unroll
        for (int e = 0; e < NEXP; e++) {
            if (e == i0) continue;
            if (i1 < 0 || p[e] > p[i1]) i1 = e;
        }
        d_gates[2 * t + 0] = p[i0];
        d_gates[2 * t + 1] = p[i1];
        d_assign_e[2 * t + 0] = i0;
        d_assign_e[2 * t + 1] = i1;
        atomicAdd(&d_counts[i0], 1);
        atomicAdd(&d_counts[i1], 1);
    }
}

__global__ void scan_kernel() {
    if (threadIdx.x == 0) {
        int s = 0;
        for (int e = 0; e < NEXP; e++) { d_offsets[e] = s; s += d_counts[e]; }
        d_offsets[NEXP] = s;
    }
}

__global__ void place_kernel() {
    int a = blockIdx.x * blockDim.x + threadIdx.x;
    if (a >= NASSIGN) return;
    int e = d_assign_e[a];
    int pos = atomicAdd(&d_cursor[e], 1);
    int r = d_offsets[e] + pos;
    d_rows_token[r] = a >> 1;
    d_rowof[a] = r;
}

// ================= fp16 2-pass HMMA grouped GEMM ==================================
// C = act((Ah+Al) * Bh^T + bias).  A hi/lo fp16 planes, B single fp16 plane.
// 128x128x32 CTA tile, 256 thr (8 warps 2x4), m16n8k16, 2 passes, double-buffered.
// SMEM stage: Ah@0, Al@10240, Bh@20480; 80 B/row (64 data + 16 pad).
#define RS      80
#define T_ALO   10240
#define T_BHI   20480
#define STAGE_B 30720
#define GEMM_SMEM (2 * STAGE_B)

__global__ __launch_bounds__(256, 1)
void gemm_tc(const __half* __restrict__ Ahi, const __half* __restrict__ Alo,
             int lda, const int* __restrict__ gather,
             const __half* __restrict__ Bh_base, size_t wstride,
             const float* __restrict__ bias_base, size_t bstride,
             float* __restrict__ Cf, __half* __restrict__ Chi, __half* __restrict__ Clo,
             int ldc,
             const int* __restrict__ row_lo_p, const int* __restrict__ row_hi_p,
             int fixedM, int K, int do_gelu)
{
    extern __shared__ char smem[];
    int e  = blockIdx.z;
    int lo = row_lo_p ? row_lo_p[e] : 0;
    int hi = row_hi_p ? row_hi_p[e] : fixedM;
    int m0 = lo + blockIdx.y * 128;
    if (m0 >= hi) return;
    int n0 = blockIdx.x * 128;
    const __half* Bh = Bh_base + (size_t)e * wstride;
    const float* bias = bias_base + (size_t)e * bstride;

    uint32_t sbase = smem_u32(smem);
    int tid  = threadIdx.x;
    int wid  = tid >> 5;
    int lane = tid & 31;
    int tig  = lane & 3;
    int wm   = wid >> 2;      // 0..1
    int wn   = wid & 3;       // 0..3

    // ---- global-load coords: thread owns row tid>>1, 32B half-row (two uint4) ------
    int r    = tid >> 1;           // 0..127
    int c0   = (tid & 1) * 16;     // element base: 0 or 16 (16 halves = 32 B)
    int arow = m0 + r;
    int avalid = (arow < hi);
    int asrc = avalid ? (gather ? gather[arow] : arow) : 0;
    const __half* pAh = Ahi + (size_t)asrc * lda + c0;
    const __half* pAl = Alo + (size_t)asrc * lda + c0;
    const __half* pBh = Bh + (size_t)(n0 + r) * K + c0;
    uint32_t soff = (uint32_t)(r * RS + c0 * 2);   // byte offset of this half-row

    // ---- ldmatrix lane offsets -------------------------------------------------------
    uint32_t aoff[4], boff[4];
    #pragma unroll
    for (int mi = 0; mi < 4; mi++)
        aoff[mi] = (uint32_t)((wm * 64 + mi * 16 + (lane & 15)) * RS + (lane >> 4) * 16);
    #pragma unroll
    for (int ni = 0; ni < 4; ni++)
        boff[ni] = (uint32_t)((wn * 32 + ni * 8 + (lane & 7)) * RS + (lane >> 3) * 16);

    float acc[4][4][4];
    #pragma unroll
    for (int mi = 0; mi < 4; mi++)
        #pragma unroll
        for (int ni = 0; ni < 4; ni++)
            #pragma unroll
            for (int q = 0; q < 4; q++) acc[mi][ni][q] = 0.f;

    int nk = K >> 5;
    uint4 vAh0, vAh1, vAl0, vAl1, vBh0, vBh1;
    const uint4 z4 = make_uint4(0u, 0u, 0u, 0u);

    // prologue: tile 0 -> stage 0
    vAh0 = avalid ? *(const uint4*)(pAh)     : z4;
    vAh1 = avalid ? *(const uint4*)(pAh + 8) : z4;
    vAl0 = avalid ? *(const uint4*)(pAl)     : z4;
    vAl1 = avalid ? *(const uint4*)(pAl + 8) : z4;
    vBh0 = *(const uint4*)(pBh);
    vBh1 = *(const uint4*)(pBh + 8);
    *(uint4*)(smem + soff)              = vAh0;
    *(uint4*)(smem + soff + 16)         = vAh1;
    *(uint4*)(smem + T_ALO + soff)      = vAl0;
    *(uint4*)(smem + T_ALO + soff + 16) = vAl1;
    *(uint4*)(smem + T_BHI + soff)      = vBh0;
    *(uint4*)(smem + T_BHI + soff + 16) = vBh1;
    __syncthreads();

    for (int kt = 0; kt < nk; kt++) {
        if (kt + 1 < nk) {
            int kb = (kt + 1) << 5;
            vAh0 = avalid ? *(const uint4*)(pAh + kb)     : z4;
            vAh1 = avalid ? *(const uint4*)(pAh + kb + 8) : z4;
            vAl0 = avalid ? *(const uint4*)(pAl + kb)     : z4;
            vAl1 = avalid ? *(const uint4*)(pAl + kb + 8) : z4;
            vBh0 = *(const uint4*)(pBh + kb);
            vBh1 = *(const uint4*)(pBh + kb + 8);
        }

        uint32_t st = sbase + (uint32_t)((kt & 1) * STAGE_B);

        uint32_t bhf[4][4];
        #pragma unroll
        for (int ni = 0; ni < 4; ni++)
            ldsm4(bhf[ni], st + T_BHI + boff[ni]);

        #pragma unroll
        for (int ks = 0; ks < 2; ks++) {
            uint32_t ahf[4][4], alf[4][4];
            #pragma unroll
            for (int mi = 0; mi < 4; mi++) {
                ldsm4(ahf[mi], st + aoff[mi] + ks * 32);
                ldsm4(alf[mi], st + T_ALO + aoff[mi] + ks * 32);
            }
            #pragma unroll
            for (int mi = 0; mi < 4; mi++)
                #pragma unroll
                for (int ni = 0; ni < 4; ni++)
                    mma16816(acc[mi][ni], ahf[mi], &bhf[ni][2 * ks]);
            #pragma unroll
            for (int mi = 0; mi < 4; mi++)
                #pragma unroll
                for (int ni = 0; ni < 4; ni++)
                    mma16816(acc[mi][ni], alf[mi], &bhf[ni][2 * ks]);
        }

        if (kt + 1 < nk) {
            char* s2 = smem + ((kt + 1) & 1) * STAGE_B;
            *(uint4*)(s2 + soff)              = vAh0;
            *(uint4*)(s2 + soff + 16)         = vAh1;
            *(uint4*)(s2 + T_ALO + soff)      = vAl0;
            *(uint4*)(s2 + T_ALO + soff + 16) = vAl1;
            *(uint4*)(s2 + T_BHI + soff)      = vBh0;
            *(uint4*)(s2 + T_BHI + soff + 16) = vBh1;
            __syncthreads();
        }
    }

    // ---------------- epilogue ----------------------------------------------------------
    int g = lane >> 2;
    #pragma unroll
    for (int mi = 0; mi < 4; mi++) {
        int row0 = m0 + wm * 64 + mi * 16 + g;
        int row1 = row0 + 8;
        #pragma unroll
        for (int ni = 0; ni < 4; ni++) {
            int cn = n0 + wn * 32 + ni * 8 + tig * 2;
            float b0 = bias[cn], b1 = bias[cn + 1];
            #pragma unroll
            for (int h = 0; h < 2; h++) {
                int row = h ? row1 : row0;
                if (row >= hi) continue;
                float v0 = acc[mi][ni][2 * h + 0] + b0;
                float v1 = acc[mi][ni][2 * h + 1] + b1;
                if (do_gelu) { v0 = gelu_tanh(v0); v1 = gelu_tanh(v1); }
                if (Chi) {
                    uint32_t hp, lp;
                    split2h(v0, v1, hp, lp);
                    *(uint32_t*)(Chi + (size_t)row * ldc + cn) = hp;
                    *(uint32_t*)(Clo + (size_t)row * ldc + cn) = lp;
                } else {
                    *(float2*)(Cf + (size_t)row * ldc + cn) = make_float2(v0, v1);
                }
            }
        }
    }
}

// ---------------- combine ------------------------------------------------------------
__global__ void combine_kernel(float* __restrict__ out) {
    int t = blockIdx.x;
    float g0 = d_gates[2 * t + 0];
    float g1 = d_gates[2 * t + 1];
    const float* y0 = d_ybuf + (size_t)d_rowof[2 * t + 0] * DMODEL;
    const float* y1 = d_ybuf + (size_t)d_rowof[2 * t + 1] * DMODEL;
    float* o = out + (size_t)t * DMODEL;
    for (int d = threadIdx.x * 4; d < DMODEL; d += blockDim.x * 4) {
        float4 ov = *(const float4*)(o + d);
        float4 a  = *(const float4*)(y0 + d);
        float4 b  = *(const float4*)(y1 + d);
        ov.x = SCALE_F * (ov.x + g0 * a.x + g1 * b.x);
        ov.y = SCALE_F * (ov.y + g0 * a.y + g1 * b.y);
        ov.z = SCALE_F * (ov.z + g0 * a.z + g1 * b.z);
        ov.w = SCALE_F * (ov.w + g0 * a.w + g1 * b.w);
        *(float4*)(o + d) = ov;
    }
}

// ---------------- launcher --------------------------------------------------------------
extern "C" void kernel_launch(void* const* d_in, const int* in_sizes, int n_in,
                              void* d_out, int out_size)
{
    const float* x   = (const float*)d_in[0];
    const float* wr  = (const float*)d_in[1];
    const float* W1  = (const float*)d_in[2];
    const float* b1  = (const float*)d_in[3];
    const float* W2  = (const float*)d_in[4];
    const float* b2  = (const float*)d_in[5];
    const float* Ws1 = (const float*)d_in[6];
    const float* bs1 = (const float*)d_in[7];
    const float* Ws2 = (const float*)d_in[8];
    const float* bs2 = (const float*)d_in[9];
    float* out = (float*)d_out;

    __half *W1h, *W2h, *Ws1h, *Ws2h, *xh, *xl, *Hh, *Hl;
    float *ybuf;
    int *offsets, *rows_token;
    cudaGetSymbolAddress((void**)&W1h, d_W1h);
    cudaGetSymbolAddress((void**)&W2h, d_W2h);
    cudaGetSymbolAddress((void**)&Ws1h, d_Ws1h);
    cudaGetSymbolAddress((void**)&Ws2h, d_Ws2h);
    cudaGetSymbolAddress((void**)&xh, d_xh);
    cudaGetSymbolAddress((void**)&xl, d_xl);
    cudaGetSymbolAddress((void**)&Hh, d_Hh);
    cudaGetSymbolAddress((void**)&Hl, d_Hl);
    cudaGetSymbolAddress((void**)&ybuf, d_ybuf);
    cudaGetSymbolAddress((void**)&offsets, d_offsets);
    cudaGetSymbolAddress((void**)&rows_token, d_rows_token);

    cudaFuncSetAttribute(gemm_tc, cudaFuncAttributeMaxDynamicSharedMemorySize, GEMM_SMEM);

    // 1-5) conversions (ordered so launch #6 = shared up-GEMM for ncu -s 5 -c 1)
    split_f16<<<2048, 256>>>((const float4*)x,  (uint2*)xh,  (uint2*)xl, NTOK * DMODEL / 4);
    cvt_f16<<<4096, 256>>>((const float4*)Ws1, (uint2*)Ws1h, DFF * DMODEL / 4);
    cvt_f16<<<4096, 256>>>((const float4*)Ws2, (uint2*)Ws2h, DMODEL * DFF / 4);
    cvt_f16<<<8192, 256>>>((const float4*)W1,  (uint2*)W1h,  NEXP * DFF * DMODEL / 4);
    cvt_f16<<<8192, 256>>>((const float4*)W2,  (uint2*)W2h,  NEXP * DMODEL * DFF / 4);

    // 6) shared up: H(hi/lo fp16) = gelu(x Ws1^T + bs1)
    {
        dim3 g1(DFF / 128, NTOK / 128, 1);
        gemm_tc<<<g1, 256, GEMM_SMEM>>>(xh, xl, DMODEL, nullptr,
                                        Ws1h, 0, bs1, 0,
                                        nullptr, Hh, Hl, DFF,
                                        nullptr, nullptr, NTOK, DMODEL, 1);
    }

    // 7-10) routing
    init_kernel<<<1, 32>>>();
    router_kernel<<<NTOK, 256>>>(x, wr);
    scan_kernel<<<1, 32>>>();
    place_kernel<<<(NASSIGN + 255) / 256, 256>>>();

    // 11) shared down: out = H Ws2^T + bs2
    {
        dim3 g2(DMODEL / 128, NTOK / 128, 1);
        gemm_tc<<<g2, 256, GEMM_SMEM>>>(Hh, Hl, DFF, nullptr,
                                        Ws2h, 0, bs2, 0,
                                        out, nullptr, nullptr, DMODEL,
                                        nullptr, nullptr, NTOK, DFF, 0);
    }

    // 12-13) routed experts
    {
        dim3 g1(DFF / 128, NASSIGN / 128, NEXP);
        gemm_tc<<<g1, 256, GEMM_SMEM>>>(xh, xl, DMODEL, rows_token,
                                        W1h, (size_t)DFF * DMODEL, b1, (size_t)DFF,
                                        nullptr, Hh, Hl, DFF,
                                        offsets, offsets + 1, 0, DMODEL, 1);
        dim3 g2(DMODEL / 128, NASSIGN / 128, NEXP);
        gemm_tc<<<g2, 256, GEMM_SMEM>>>(Hh, Hl, DFF, nullptr,
                                        W2h, (size_t)DMODEL * DFF, b2, (size_t)DMODEL,
                                        ybuf, nullptr, nullptr, DMODEL,
                                        offsets, offsets + 1, 0, DFF, 0);
    }

    // 14) combine
    combine_kernel<<<NTOK, 256>>>(out);
}

// round 7
// speedup vs baseline: 4.7783x; 1.6706x over previous
#include <cuda_runtime.h>
#include <cuda_fp16.h>
#include <stdint.h>
#include <math.h>

#define NTOK   4096
#define DMODEL 1024
#define DFF    4096
#define NEXP   8
#define NASSIGN (NTOK*2)
#define SCALE_F 0.894427190999915878f

// ---------------- device scratch (fp16 single planes) -----------------------------
__device__ __half d_W1h[(size_t)NEXP * DFF * DMODEL];
__device__ __half d_W2h[(size_t)NEXP * DMODEL * DFF];
__device__ __half d_Ws1h[(size_t)DFF * DMODEL];
__device__ __half d_Ws2h[(size_t)DMODEL * DFF];
__device__ __half d_xh[(size_t)NTOK * DMODEL];
__device__ __half d_Hh[(size_t)NASSIGN * DFF];
__device__ float d_ybuf[(size_t)NASSIGN * DMODEL];
__device__ float d_gates[NASSIGN];
__device__ int   d_assign_e[NASSIGN];
__device__ int   d_counts[NEXP];
__device__ int   d_cursor[NEXP];
__device__ int   d_offsets[NEXP + 1];
__device__ int   d_rows_token[NASSIGN];
__device__ int   d_rowof[NASSIGN];

// ---------------- helpers -----------------------------------------------------------
__device__ __forceinline__ float gelu_tanh(float v) {
    const float c0 = 0.7978845608028654f;
    const float c1 = 0.044715f;
    float t = tanhf(c0 * (v + c1 * v * v * v));
    return 0.5f * v * (1.0f + t);
}

__device__ __forceinline__ void mma16816(float* c, const uint32_t* a, const uint32_t* b) {
    asm volatile(
        "mma.sync.aligned.m16n8k16.row.col.f32.f16.f16.f32 "
        "{%0,%1,%2,%3}, {%4,%5,%6,%7}, {%8,%9}, {%0,%1,%2,%3};"
        : "+f"(c[0]), "+f"(c[1]), "+f"(c[2]), "+f"(c[3])
        : "r"(a[0]), "r"(a[1]), "r"(a[2]), "r"(a[3]), "r"(b[0]), "r"(b[1]));
}

__device__ __forceinline__ void ldsm4(uint32_t* r, uint32_t addr) {
    asm volatile("ldmatrix.sync.aligned.m8n8.x4.shared.b16 {%0,%1,%2,%3}, [%4];"
                 : "=r"(r[0]), "=r"(r[1]), "=r"(r[2]), "=r"(r[3]) : "r"(addr));
}

__device__ __forceinline__ uint32_t smem_u32(const void* p) {
    uint32_t a;
    asm("{ .reg .u64 t; cvta.to.shared.u64 t, %1; cvt.u32.u64 %0, t; }" : "=r"(a) : "l"(p));
    return a;
}

// ---------------- conversion kernel ----------------------------------------------------
__global__ void cvt_f16(const float4* __restrict__ src, uint2* __restrict__ dst, int n4) {
    for (int i = blockIdx.x * blockDim.x + threadIdx.x; i < n4; i += gridDim.x * blockDim.x) {
        float4 v = src[i];
        __half2 a = __floats2half2_rn(v.x, v.y);
        __half2 b = __floats2half2_rn(v.z, v.w);
        dst[i] = make_uint2(*(uint32_t*)&a, *(uint32_t*)&b);
    }
}

// ---------------- routing kernels -------------------------------------------------------
__global__ void init_kernel() {
    int i = threadIdx.x;
    if (i < NEXP) { d_counts[i] = 0; d_cursor[i] = 0; }
}

__global__ void router_kernel(const float* __restrict__ x,
                              const float* __restrict__ wr) {
    int t = blockIdx.x;
    int warp = threadIdx.x >> 5;
    int lane = threadIdx.x & 31;
    const float* xr = x + (size_t)t * DMODEL;
    const float* w  = wr + (size_t)warp * DMODEL;
    float s = 0.f;
    #pragma unroll 4
    for (int i = lane; i < DMODEL; i += 32) s += xr[i] * w[i];
    #pragma unroll
    for (int o = 16; o > 0; o >>= 1) s += __shfl_xor_sync(0xFFFFFFFFu, s, o);

    __shared__ float logits[NEXP];
    if (lane == 0) logits[warp] = s;
    __syncthreads();

    if (threadIdx.x == 0) {
        float mx = logits[0];
        #pragma unroll
        for (int e = 1; e < NEXP; e++) mx = fmaxf(mx, logits[e]);
        float p[NEXP]; float sum = 0.f;
        #pragma unroll
        for (int e = 0; e < NEXP; e++) { p[e] = expf(logits[e] - mx); sum += p[e]; }
        float inv = 1.f / sum;
        #pragma unroll
        for (int e = 0; e < NEXP; e++) p[e] *= inv;
        int i0 = 0;
        #pragma unroll
        for (int e = 1; e < NEXP; e++) if (p[e] > p[i0]) i0 = e;
        int i1 = -1;
        #pragma unroll
        for (int e = 0; e < NEXP; e++) {
            if (e == i0) continue;
            if (i1 < 0 || p[e] > p[i1]) i1 = e;
        }
        d_gates[2 * t + 0] = p[i0];
        d_gates[2 * t + 1] = p[i1];
        d_assign_e[2 * t + 0] = i0;
        d_assign_e[2 * t + 1] = i1;
        atomicAdd(&d_counts[i0], 1);
        atomicAdd(&d_counts[i1], 1);
    }
}

__global__ void scan_kernel() {
    if (threadIdx.x == 0) {
        int s = 0;
        for (int e = 0; e < NEXP; e++) { d_offsets[e] = s; s += d_counts[e]; }
        d_offsets[NEXP] = s;
    }
}

__global__ void place_kernel() {
    int a = blockIdx.x * blockDim.x + threadIdx.x;
    if (a >= NASSIGN) return;
    int e = d_assign_e[a];
    int pos = atomicAdd(&d_cursor[e], 1);
    int r = d_offsets[e] + pos;
    d_rows_token[r] = a >> 1;
    d_rowof[a] = r;
}

// ================= fp16 single-pass HMMA grouped GEMM ================================
// C = act(A * B^T + bias).  A, B single fp16 planes.
// 128x128x32 CTA tile, 256 thr (8 warps 2x4), m16n8k16, double-buffered.
// SMEM stage: A@0, B@10240; 80 B/row (64 data + 16 pad). 2 stages = 40 KB -> 2 CTAs/SM.
#define RS      80
#define T_BHI   10240
#define STAGE_B 20480
#define GEMM_SMEM (2 * STAGE_B)

__global__ __launch_bounds__(256, 2)
void gemm_tc(const __half* __restrict__ Ah, int lda, const int* __restrict__ gather,
             const __half* __restrict__ Bh_base, size_t wstride,
             const float* __restrict__ bias_base, size_t bstride,
             float* __restrict__ Cf, __half* __restrict__ Ch, int ldc,
             const int* __restrict__ row_lo_p, const int* __restrict__ row_hi_p,
             int fixedM, int K, int do_gelu)
{
    extern __shared__ char smem[];
    int e  = blockIdx.z;
    int lo = row_lo_p ? row_lo_p[e] : 0;
    int hi = row_hi_p ? row_hi_p[e] : fixedM;
    int m0 = lo + blockIdx.y * 128;
    if (m0 >= hi) return;
    int n0 = blockIdx.x * 128;
    const __half* Bh = Bh_base + (size_t)e * wstride;
    const float* bias = bias_base + (size_t)e * bstride;

    uint32_t sbase = smem_u32(smem);
    int tid  = threadIdx.x;
    int wid  = tid >> 5;
    int lane = tid & 31;
    int tig  = lane & 3;
    int wm   = wid >> 2;      // 0..1
    int wn   = wid & 3;       // 0..3

    // ---- global-load coords: thread owns row tid>>1, 32B half-row (two uint4) ------
    int r    = tid >> 1;           // 0..127
    int c0   = (tid & 1) * 16;     // element base: 0 or 16
    int arow = m0 + r;
    int avalid = (arow < hi);
    int asrc = avalid ? (gather ? gather[arow] : arow) : 0;
    const __half* pAh = Ah + (size_t)asrc * lda + c0;
    const __half* pBh = Bh + (size_t)(n0 + r) * K + c0;
    uint32_t soff = (uint32_t)(r * RS + c0 * 2);

    // ---- ldmatrix lane offsets -------------------------------------------------------
    uint32_t aoff[4], boff[4];
    #pragma unroll
    for (int mi = 0; mi < 4; mi++)
        aoff[mi] = (uint32_t)((wm * 64 + mi * 16 + (lane & 15)) * RS + (lane >> 4) * 16);
    #pragma unroll
    for (int ni = 0; ni < 4; ni++)
        boff[ni] = (uint32_t)((wn * 32 + ni * 8 + (lane & 7)) * RS + (lane >> 3) * 16);

    float acc[4][4][4];
    #pragma unroll
    for (int mi = 0; mi < 4; mi++)
        #pragma unroll
        for (int ni = 0; ni < 4; ni++)
            #pragma unroll
            for (int q = 0; q < 4; q++) acc[mi][ni][q] = 0.f;

    int nk = K >> 5;
    uint4 vA0, vA1, vB0, vB1;
    const uint4 z4 = make_uint4(0u, 0u, 0u, 0u);

    // prologue: tile 0 -> stage 0
    vA0 = avalid ? *(const uint4*)(pAh)     : z4;
    vA1 = avalid ? *(const uint4*)(pAh + 8) : z4;
    vB0 = *(const uint4*)(pBh);
    vB1 = *(const uint4*)(pBh + 8);
    *(uint4*)(smem + soff)              = vA0;
    *(uint4*)(smem + soff + 16)         = vA1;
    *(uint4*)(smem + T_BHI + soff)      = vB0;
    *(uint4*)(smem + T_BHI + soff + 16) = vB1;
    __syncthreads();

    for (int kt = 0; kt < nk; kt++) {
        if (kt + 1 < nk) {
            int kb = (kt + 1) << 5;
            vA0 = avalid ? *(const uint4*)(pAh + kb)     : z4;
            vA1 = avalid ? *(const uint4*)(pAh + kb + 8) : z4;
            vB0 = *(const uint4*)(pBh + kb);
            vB1 = *(const uint4*)(pBh + kb + 8);
        }

        uint32_t st = sbase + (uint32_t)((kt & 1) * STAGE_B);

        uint32_t bhf[4][4];
        #pragma unroll
        for (int ni = 0; ni < 4; ni++)
            ldsm4(bhf[ni], st + T_BHI + boff[ni]);

        #pragma unroll
        for (int ks = 0; ks < 2; ks++) {
            uint32_t ahf[4][4];
            #pragma unroll
            for (int mi = 0; mi < 4; mi++)
                ldsm4(ahf[mi], st + aoff[mi] + ks * 32);
            #pragma unroll
            for (int mi = 0; mi < 4; mi++)
                #pragma unroll
                for (int ni = 0; ni < 4; ni++)
                    mma16816(acc[mi][ni], ahf[mi], &bhf[ni][2 * ks]);
        }

        if (kt + 1 < nk) {
            char* s2 = smem + ((kt + 1) & 1) * STAGE_B;
            *(uint4*)(s2 + soff)              = vA0;
            *(uint4*)(s2 + soff + 16)         = vA1;
            *(uint4*)(s2 + T_BHI + soff)      = vB0;
            *(uint4*)(s2 + T_BHI + soff + 16) = vB1;
            __syncthreads();
        }
    }

    // ---------------- epilogue ----------------------------------------------------------
    int g = lane >> 2;
    #pragma unroll
    for (int mi = 0; mi < 4; mi++) {
        int row0 = m0 + wm * 64 + mi * 16 + g;
        int row1 = row0 + 8;
        #pragma unroll
        for (int ni = 0; ni < 4; ni++) {
            int cn = n0 + wn * 32 + ni * 8 + tig * 2;
            float b0 = bias[cn], b1 = bias[cn + 1];
            #pragma unroll
            for (int h = 0; h < 2; h++) {
                int row = h ? row1 : row0;
                if (row >= hi) continue;
                float v0 = acc[mi][ni][2 * h + 0] + b0;
                float v1 = acc[mi][ni][2 * h + 1] + b1;
                if (do_gelu) { v0 = gelu_tanh(v0); v1 = gelu_tanh(v1); }
                if (Ch) {
                    __half2 hp = __floats2half2_rn(v0, v1);
                    *(uint32_t*)(Ch + (size_t)row * ldc + cn) = *(uint32_t*)&hp;
                } else {
                    *(float2*)(Cf + (size_t)row * ldc + cn) = make_float2(v0, v1);
                }
            }
        }
    }
}

// ---------------- combine ---------------------------------------------------------------
__global__ void combine_kernel(float* __restrict__ out) {
    int t = blockIdx.x;
    float g0 = d_gates[2 * t + 0];
    float g1 = d_gates[2 * t + 1];
    const float* y0 = d_ybuf + (size_t)d_rowof[2 * t + 0] * DMODEL;
    const float* y1 = d_ybuf + (size_t)d_rowof[2 * t + 1] * DMODEL;
    float* o = out + (size_t)t * DMODEL;
    for (int d = threadIdx.x * 4; d < DMODEL; d += blockDim.x * 4) {
        float4 ov = *(const float4*)(o + d);
        float4 a  = *(const float4*)(y0 + d);
        float4 b  = *(const float4*)(y1 + d);
        ov.x = SCALE_F * (ov.x + g0 * a.x + g1 * b.x);
        ov.y = SCALE_F * (ov.y + g0 * a.y + g1 * b.y);
        ov.z = SCALE_F * (ov.z + g0 * a.z + g1 * b.z);
        ov.w = SCALE_F * (ov.w + g0 * a.w + g1 * b.w);
        *(float4*)(o + d) = ov;
    }
}

// ---------------- launcher ------------------------------------------------------------------
extern "C" void kernel_launch(void* const* d_in, const int* in_sizes, int n_in,
                              void* d_out, int out_size)
{
    const float* x   = (const float*)d_in[0];
    const float* wr  = (const float*)d_in[1];
    const float* W1  = (const float*)d_in[2];
    const float* b1  = (const float*)d_in[3];
    const float* W2  = (const float*)d_in[4];
    const float* b2  = (const float*)d_in[5];
    const float* Ws1 = (const float*)d_in[6];
    const float* bs1 = (const float*)d_in[7];
    const float* Ws2 = (const float*)d_in[8];
    const float* bs2 = (const float*)d_in[9];
    float* out = (float*)d_out;

    __half *W1h, *W2h, *Ws1h, *Ws2h, *xh, *Hh;
    float *ybuf;
    int *offsets, *rows_token;
    cudaGetSymbolAddress((void**)&W1h, d_W1h);
    cudaGetSymbolAddress((void**)&W2h, d_W2h);
    cudaGetSymbolAddress((void**)&Ws1h, d_Ws1h);
    cudaGetSymbolAddress((void**)&Ws2h, d_Ws2h);
    cudaGetSymbolAddress((void**)&xh, d_xh);
    cudaGetSymbolAddress((void**)&Hh, d_Hh);
    cudaGetSymbolAddress((void**)&ybuf, d_ybuf);
    cudaGetSymbolAddress((void**)&offsets, d_offsets);
    cudaGetSymbolAddress((void**)&rows_token, d_rows_token);

    cudaFuncSetAttribute(gemm_tc, cudaFuncAttributeMaxDynamicSharedMemorySize, GEMM_SMEM);

    // 1-5) conversions (launch #6 = shared up-GEMM for ncu -s 5 -c 1)
    cvt_f16<<<2048, 256>>>((const float4*)x,   (uint2*)xh,   NTOK * DMODEL / 4);
    cvt_f16<<<4096, 256>>>((const float4*)Ws1, (uint2*)Ws1h, DFF * DMODEL / 4);
    cvt_f16<<<4096, 256>>>((const float4*)Ws2, (uint2*)Ws2h, DMODEL * DFF / 4);
    cvt_f16<<<8192, 256>>>((const float4*)W1,  (uint2*)W1h,  NEXP * DFF * DMODEL / 4);
    cvt_f16<<<8192, 256>>>((const float4*)W2,  (uint2*)W2h,  NEXP * DMODEL * DFF / 4);

    // 6) shared up: H(fp16) = gelu(x Ws1^T + bs1)
    {
        dim3 g1(DFF / 128, NTOK / 128, 1);
        gemm_tc<<<g1, 256, GEMM_SMEM>>>(xh, DMODEL, nullptr,
                                        Ws1h, 0, bs1, 0,
                                        nullptr, Hh, DFF,
                                        nullptr, nullptr, NTOK, DMODEL, 1);
    }

    // 7-10) routing
    init_kernel<<<1, 32>>>();
    router_kernel<<<NTOK, 256>>>(x, wr);
    scan_kernel<<<1, 32>>>();
    place_kernel<<<(NASSIGN + 255) / 256, 256>>>();

    // 11) shared down: out = H Ws2^T + bs2
    {
        dim3 g2(DMODEL / 128, NTOK / 128, 1);
        gemm_tc<<<g2, 256, GEMM_SMEM>>>(Hh, DFF, nullptr,
                                        Ws2h, 0, bs2, 0,
                                        out, nullptr, DMODEL,
                                        nullptr, nullptr, NTOK, DFF, 0);
    }

    // 12-13) routed experts
    {
        dim3 g1(DFF / 128, NASSIGN / 128, NEXP);
        gemm_tc<<<g1, 256, GEMM_SMEM>>>(xh, DMODEL, rows_token,
                                        W1h, (size_t)DFF * DMODEL, b1, (size_t)DFF,
                                        nullptr, Hh, DFF,
                                        offsets, offsets + 1, 0, DMODEL, 1);
        dim3 g2(DMODEL / 128, NASSIGN / 128, NEXP);
        gemm_tc<<<g2, 256, GEMM_SMEM>>>(Hh, DFF, nullptr,
                                        W2h, (size_t)DMODEL * DFF, b2, (size_t)DMODEL,
                                        ybuf, nullptr, DMODEL,
                                        offsets, offsets + 1, 0, DFF, 0);
    }

    // 14) combine
    combine_kernel<<<NTOK, 256>>>(out);
}

// round 8
// speedup vs baseline: 4.8180x; 1.0083x over previous
#include <cuda_runtime.h>
#include <cuda_fp16.h>
#include <stdint.h>
#include <math.h>

#define NTOK   4096
#define DMODEL 1024
#define DFF    4096
#define NEXP   8
#define NEXPX  9                 // 8 routed + 1 shared
#define NASSIGN (NTOK*2)
#define NROWS  (NASSIGN + NTOK)  // 12288 unified rows
#define SCALE_F 0.894427190999915878f

// ---------------- device scratch ----------------------------------------------------
__device__ __half d_W1x[(size_t)NEXPX * DFF * DMODEL];   // slots 0-7: W1, slot 8: Ws1
__device__ __half d_W2x[(size_t)NEXPX * DMODEL * DFF];   // slots 0-7: W2, slot 8: Ws2
__device__ float  d_b1x[NEXPX * DFF];
__device__ float  d_b2x[NEXPX * DMODEL];
__device__ __half d_xh[(size_t)NTOK * DMODEL];
__device__ __half d_Hh[(size_t)NROWS * DFF];
__device__ float  d_ybuf[(size_t)NROWS * DMODEL];
__device__ float  d_gates[NASSIGN];
__device__ int    d_assign_e[NASSIGN];
__device__ int    d_offsets[NEXPX + 1];                  // [0..8] routed scan, [9]=NROWS
__device__ int    d_rows_token[NROWS];                   // GEMM row -> token
__device__ int    d_rowof[NASSIGN];                      // assignment -> GEMM row

// ---------------- helpers --------------------------------------------------------------
__device__ __forceinline__ float gelu_tanh(float v) {
    const float c0 = 0.7978845608028654f;
    const float c1 = 0.044715f;
    float t = tanhf(c0 * (v + c1 * v * v * v));
    return 0.5f * v * (1.0f + t);
}

__device__ __forceinline__ void mma16816(float* c, const uint32_t* a, const uint32_t* b) {
    asm volatile(
        "mma.sync.aligned.m16n8k16.row.col.f32.f16.f16.f32 "
        "{%0,%1,%2,%3}, {%4,%5,%6,%7}, {%8,%9}, {%0,%1,%2,%3};"
        : "+f"(c[0]), "+f"(c[1]), "+f"(c[2]), "+f"(c[3])
        : "r"(a[0]), "r"(a[1]), "r"(a[2]), "r"(a[3]), "r"(b[0]), "r"(b[1]));
}

__device__ __forceinline__ void ldsm4(uint32_t* r, uint32_t addr) {
    asm volatile("ldmatrix.sync.aligned.m8n8.x4.shared.b16 {%0,%1,%2,%3}, [%4];"
                 : "=r"(r[0]), "=r"(r[1]), "=r"(r[2]), "=r"(r[3]) : "r"(addr));
}

__device__ __forceinline__ uint32_t smem_u32(const void* p) {
    uint32_t a;
    asm("{ .reg .u64 t; cvta.to.shared.u64 t, %1; cvt.u32.u64 %0, t; }" : "=r"(a) : "l"(p));
    return a;
}

// ---------------- launch 1: router (no atomics) ------------------------------------------
__global__ void router_kernel(const float* __restrict__ x,
                              const float* __restrict__ wr) {
    int t = blockIdx.x;
    int warp = threadIdx.x >> 5;
    int lane = threadIdx.x & 31;
    const float* xr = x + (size_t)t * DMODEL;
    const float* w  = wr + (size_t)warp * DMODEL;
    float s = 0.f;
    #pragma unroll 4
    for (int i = lane; i < DMODEL; i += 32) s += xr[i] * w[i];
    #pragma unroll
    for (int o = 16; o > 0; o >>= 1) s += __shfl_xor_sync(0xFFFFFFFFu, s, o);

    __shared__ float logits[NEXP];
    if (lane == 0) logits[warp] = s;
    __syncthreads();

    if (threadIdx.x == 0) {
        float mx = logits[0];
        #pragma unroll
        for (int e = 1; e < NEXP; e++) mx = fmaxf(mx, logits[e]);
        float p[NEXP]; float sum = 0.f;
        #pragma unroll
        for (int e = 0; e < NEXP; e++) { p[e] = expf(logits[e] - mx); sum += p[e]; }
        float inv = 1.f / sum;
        #pragma unroll
        for (int e = 0; e < NEXP; e++) p[e] *= inv;
        int i0 = 0;
        #pragma unroll
        for (int e = 1; e < NEXP; e++) if (p[e] > p[i0]) i0 = e;
        int i1 = -1;
        #pragma unroll
        for (int e = 0; e < NEXP; e++) {
            if (e == i0) continue;
            if (i1 < 0 || p[e] > p[i1]) i1 = e;
        }
        d_gates[2 * t + 0] = p[i0];
        d_gates[2 * t + 1] = p[i1];
        d_assign_e[2 * t + 0] = i0;
        d_assign_e[2 * t + 1] = i1;
    }
}

// ---------------- launch 2: single-block count + scan + place ----------------------------
__global__ void scanplace_kernel() {
    __shared__ int scount[NEXP];
    __shared__ int scursor[NEXP];
    int tid = threadIdx.x;
    if (tid < NEXP) scount[tid] = 0;
    __syncthreads();
    for (int a = tid; a < NASSIGN; a += blockDim.x)
        atomicAdd(&scount[d_assign_e[a]], 1);
    __syncthreads();
    if (tid == 0) {
        int s = 0;
        for (int e = 0; e < NEXP; e++) { d_offsets[e] = s; scursor[e] = s; s += scount[e]; }
        d_offsets[NEXP]  = s;        // == NASSIGN
        d_offsets[NEXPX] = NROWS;    // shared range [NASSIGN, NROWS)
    }
    __syncthreads();
    for (int a = tid; a < NASSIGN; a += blockDim.x) {
        int e = d_assign_e[a];
        int r = atomicAdd(&scursor[e], 1);
        d_rows_token[r] = a >> 1;
        d_rowof[a] = r;
    }
    for (int t = tid; t < NTOK; t += blockDim.x)
        d_rows_token[NASSIGN + t] = t;   // shared expert: identity gather
}

// ---------------- launch 3: x -> fp16 + bias packing --------------------------------------
__global__ void cvt_x_bias(const float4* __restrict__ x,
                           uint2* __restrict__ xh,
                           const float* __restrict__ b1, const float* __restrict__ bs1,
                           const float* __restrict__ b2, const float* __restrict__ bs2,
                           float* __restrict__ b1x, float* __restrict__ b2x) {
    const int n4 = NTOK * DMODEL / 4;
    for (int i = blockIdx.x * blockDim.x + threadIdx.x; i < n4; i += gridDim.x * blockDim.x) {
        float4 v = x[i];
        __half2 a = __floats2half2_rn(v.x, v.y);
        __half2 b = __floats2half2_rn(v.z, v.w);
        xh[i] = make_uint2(*(uint32_t*)&a, *(uint32_t*)&b);
    }
    for (int i = blockIdx.x * blockDim.x + threadIdx.x; i < NEXPX * DFF; i += gridDim.x * blockDim.x)
        b1x[i] = (i < NEXP * DFF) ? b1[i] : bs1[i - NEXP * DFF];
    for (int i = blockIdx.x * blockDim.x + threadIdx.x; i < NEXPX * DMODEL; i += gridDim.x * blockDim.x)
        b2x[i] = (i < NEXP * DMODEL) ? b2[i] : bs2[i - NEXP * DMODEL];
}

// ---------------- launches 4 & 6: weights -> 9-expert fp16 buffer --------------------------
__global__ void cvt_w9(const float4* __restrict__ w8, const float4* __restrict__ ws,
                       uint2* __restrict__ dst, int n4_routed, int n4_total) {
    for (int i = blockIdx.x * blockDim.x + threadIdx.x; i < n4_total; i += gridDim.x * blockDim.x) {
        float4 v = (i < n4_routed) ? w8[i] : ws[i - n4_routed];
        __half2 a = __floats2half2_rn(v.x, v.y);
        __half2 b = __floats2half2_rn(v.z, v.w);
        dst[i] = make_uint2(*(uint32_t*)&a, *(uint32_t*)&b);
    }
}

// ================= fp16 single-pass HMMA grouped GEMM ====================================
// 128x128x32 CTA tile, 256 thr (8 warps 2x4), m16n8k16, double-buffered, 2 CTAs/SM.
#define RS      80
#define T_BHI   10240
#define STAGE_B 20480
#define GEMM_SMEM (2 * STAGE_B)

__global__ __launch_bounds__(256, 2)
void gemm_tc(const __half* __restrict__ Ah, int lda, const int* __restrict__ gather,
             const __half* __restrict__ Bh_base, size_t wstride,
             const float* __restrict__ bias_base, size_t bstride,
             float* __restrict__ Cf, __half* __restrict__ Ch, int ldc,
             const int* __restrict__ offs, int K, int do_gelu)
{
    extern __shared__ char smem[];
    int e  = blockIdx.z;
    int lo = offs[e];
    int hi = offs[e + 1];
    int m0 = lo + blockIdx.y * 128;
    if (m0 >= hi) return;
    int n0 = blockIdx.x * 128;
    const __half* Bh = Bh_base + (size_t)e * wstride;
    const float* bias = bias_base + (size_t)e * bstride;

    uint32_t sbase = smem_u32(smem);
    int tid  = threadIdx.x;
    int wid  = tid >> 5;
    int lane = tid & 31;
    int tig  = lane & 3;
    int wm   = wid >> 2;
    int wn   = wid & 3;

    int r    = tid >> 1;
    int c0   = (tid & 1) * 16;
    int arow = m0 + r;
    int avalid = (arow < hi);
    int asrc = avalid ? (gather ? gather[arow] : arow) : 0;
    const __half* pAh = Ah + (size_t)asrc * lda + c0;
    const __half* pBh = Bh + (size_t)(n0 + r) * K + c0;
    uint32_t soff = (uint32_t)(r * RS + c0 * 2);

    uint32_t aoff[4], boff[4];
    #pragma unroll
    for (int mi = 0; mi < 4; mi++)
        aoff[mi] = (uint32_t)((wm * 64 + mi * 16 + (lane & 15)) * RS + (lane >> 4) * 16);
    #pragma unroll
    for (int ni = 0; ni < 4; ni++)
        boff[ni] = (uint32_t)((wn * 32 + ni * 8 + (lane & 7)) * RS + (lane >> 3) * 16);

    float acc[4][4][4];
    #pragma unroll
    for (int mi = 0; mi < 4; mi++)
        #pragma unroll
        for (int ni = 0; ni < 4; ni++)
            #pragma unroll
            for (int q = 0; q < 4; q++) acc[mi][ni][q] = 0.f;

    int nk = K >> 5;
    uint4 vA0, vA1, vB0, vB1;
    const uint4 z4 = make_uint4(0u, 0u, 0u, 0u);

    vA0 = avalid ? *(const uint4*)(pAh)     : z4;
    vA1 = avalid ? *(const uint4*)(pAh + 8) : z4;
    vB0 = *(const uint4*)(pBh);
    vB1 = *(const uint4*)(pBh + 8);
    *(uint4*)(smem + soff)              = vA0;
    *(uint4*)(smem + soff + 16)         = vA1;
    *(uint4*)(smem + T_BHI + soff)      = vB0;
    *(uint4*)(smem + T_BHI + soff + 16) = vB1;
    __syncthreads();

    for (int kt = 0; kt < nk; kt++) {
        if (kt + 1 < nk) {
            int kb = (kt + 1) << 5;
            vA0 = avalid ? *(const uint4*)(pAh + kb)     : z4;
            vA1 = avalid ? *(const uint4*)(pAh + kb + 8) : z4;
            vB0 = *(const uint4*)(pBh + kb);
            vB1 = *(const uint4*)(pBh + kb + 8);
        }

        uint32_t st = sbase + (uint32_t)((kt & 1) * STAGE_B);

        uint32_t bhf[4][4];
        #pragma unroll
        for (int ni = 0; ni < 4; ni++)
            ldsm4(bhf[ni], st + T_BHI + boff[ni]);

        #pragma unroll
        for (int ks = 0; ks < 2; ks++) {
            uint32_t ahf[4][4];
            #pragma unroll
            for (int mi = 0; mi < 4; mi++)
                ldsm4(ahf[mi], st + aoff[mi] + ks * 32);
            #pragma unroll
            for (int mi = 0; mi < 4; mi++)
                #pragma unroll
                for (int ni = 0; ni < 4; ni++)
                    mma16816(acc[mi][ni], ahf[mi], &bhf[ni][2 * ks]);
        }

        if (kt + 1 < nk) {
            char* s2 = smem + ((kt + 1) & 1) * STAGE_B;
            *(uint4*)(s2 + soff)              = vA0;
            *(uint4*)(s2 + soff + 16)         = vA1;
            *(uint4*)(s2 + T_BHI + soff)      = vB0;
            *(uint4*)(s2 + T_BHI + soff + 16) = vB1;
            __syncthreads();
        }
    }

    int g = lane >> 2;
    #pragma unroll
    for (int mi = 0; mi < 4; mi++) {
        int row0 = m0 + wm * 64 + mi * 16 + g;
        int row1 = row0 + 8;
        #pragma unroll
        for (int ni = 0; ni < 4; ni++) {
            int cn = n0 + wn * 32 + ni * 8 + tig * 2;
            float b0 = bias[cn], b1 = bias[cn + 1];
            #pragma unroll
            for (int h = 0; h < 2; h++) {
                int row = h ? row1 : row0;
                if (row >= hi) continue;
                float v0 = acc[mi][ni][2 * h + 0] + b0;
                float v1 = acc[mi][ni][2 * h + 1] + b1;
                if (do_gelu) { v0 = gelu_tanh(v0); v1 = gelu_tanh(v1); }
                if (Ch) {
                    __half2 hp = __floats2half2_rn(v0, v1);
                    *(uint32_t*)(Ch + (size_t)row * ldc + cn) = *(uint32_t*)&hp;
                } else {
                    *(float2*)(Cf + (size_t)row * ldc + cn) = make_float2(v0, v1);
                }
            }
        }
    }
}

// ---------------- launch 8: combine -------------------------------------------------------
__global__ void combine_kernel(float* __restrict__ out) {
    int t = blockIdx.x;
    float g0 = d_gates[2 * t + 0];
    float g1 = d_gates[2 * t + 1];
    const float* y0 = d_ybuf + (size_t)d_rowof[2 * t + 0] * DMODEL;
    const float* y1 = d_ybuf + (size_t)d_rowof[2 * t + 1] * DMODEL;
    const float* ys = d_ybuf + (size_t)(NASSIGN + t) * DMODEL;
    float* o = out + (size_t)t * DMODEL;
    for (int d = threadIdx.x * 4; d < DMODEL; d += blockDim.x * 4) {
        float4 s  = *(const float4*)(ys + d);
        float4 a  = *(const float4*)(y0 + d);
        float4 b  = *(const float4*)(y1 + d);
        float4 ov;
        ov.x = SCALE_F * (s.x + g0 * a.x + g1 * b.x);
        ov.y = SCALE_F * (s.y + g0 * a.y + g1 * b.y);
        ov.z = SCALE_F * (s.z + g0 * a.z + g1 * b.z);
        ov.w = SCALE_F * (s.w + g0 * a.w + g1 * b.w);
        *(float4*)(o + d) = ov;
    }
}

// ---------------- launcher ------------------------------------------------------------------
extern "C" void kernel_launch(void* const* d_in, const int* in_sizes, int n_in,
                              void* d_out, int out_size)
{
    const float* x   = (const float*)d_in[0];
    const float* wr  = (const float*)d_in[1];
    const float* W1  = (const float*)d_in[2];
    const float* b1  = (const float*)d_in[3];
    const float* W2  = (const float*)d_in[4];
    const float* b2  = (const float*)d_in[5];
    const float* Ws1 = (const float*)d_in[6];
    const float* bs1 = (const float*)d_in[7];
    const float* Ws2 = (const float*)d_in[8];
    const float* bs2 = (const float*)d_in[9];
    float* out = (float*)d_out;

    __half *W1x, *W2x, *xh, *Hh;
    float *ybuf, *b1x, *b2x;
    int *offsets, *rows_token;
    cudaGetSymbolAddress((void**)&W1x, d_W1x);
    cudaGetSymbolAddress((void**)&W2x, d_W2x);
    cudaGetSymbolAddress((void**)&b1x, d_b1x);
    cudaGetSymbolAddress((void**)&b2x, d_b2x);
    cudaGetSymbolAddress((void**)&xh, d_xh);
    cudaGetSymbolAddress((void**)&Hh, d_Hh);
    cudaGetSymbolAddress((void**)&ybuf, d_ybuf);
    cudaGetSymbolAddress((void**)&offsets, d_offsets);
    cudaGetSymbolAddress((void**)&rows_token, d_rows_token);

    cudaFuncSetAttribute(gemm_tc, cudaFuncAttributeMaxDynamicSharedMemorySize, GEMM_SMEM);

    // 1-2) routing
    router_kernel<<<NTOK, 256>>>(x, wr);
    scanplace_kernel<<<1, 1024>>>();

    // 3) x conversion + bias packing
    cvt_x_bias<<<2048, 256>>>((const float4*)x, (uint2*)xh, b1, bs1, b2, bs2, b1x, b2x);

    // 4) up-weights -> 9-expert fp16 (W1 + Ws1)
    cvt_w9<<<8192, 256>>>((const float4*)W1, (const float4*)Ws1, (uint2*)W1x,
                          NEXP * DFF * DMODEL / 4, NEXPX * DFF * DMODEL / 4);

    // 5) unified up-GEMM: H = gelu(x W^T + b) over 9 expert groups (ncu lands here)
    {
        dim3 g(DFF / 128, 32, NEXPX);
        gemm_tc<<<g, 256, GEMM_SMEM>>>(xh, DMODEL, rows_token,
                                       W1x, (size_t)DFF * DMODEL, b1x, DFF,
                                       nullptr, Hh, DFF,
                                       offsets, DMODEL, 1);
    }

    // 6) down-weights -> 9-expert fp16 (W2 + Ws2)
    cvt_w9<<<8192, 256>>>((const float4*)W2, (const float4*)Ws2, (uint2*)W2x,
                          NEXP * DMODEL * DFF / 4, NEXPX * DMODEL * DFF / 4);

    // 7) unified down-GEMM: y = H W^T + b
    {
        dim3 g(DMODEL / 128, 32, NEXPX);
        gemm_tc<<<g, 256, GEMM_SMEM>>>(Hh, DFF, nullptr,
                                       W2x, (size_t)DMODEL * DFF, b2x, DMODEL,
                                       ybuf, nullptr, DMODEL,
                                       offsets, DFF, 0);
    }

    // 8) combine
    combine_kernel<<<NTOK, 256>>>(out);
}

// round 9
// speedup vs baseline: 5.0076x; 1.0394x over previous
#include <cuda_runtime.h>
#include <cuda_fp16.h>
#include <stdint.h>
#include <math.h>

#define NTOK   4096
#define DMODEL 1024
#define DFF    4096
#define NEXP   8
#define NEXPX  9                 // 8 routed + 1 shared
#define NASSIGN (NTOK*2)
#define NROWS  (NASSIGN + NTOK)  // 12288 unified rows
#define SCALE_F 0.894427190999915878f

// ---------------- device scratch ----------------------------------------------------
__device__ __half d_W1x[(size_t)NEXPX * DFF * DMODEL];
__device__ __half d_W2x[(size_t)NEXPX * DMODEL * DFF];
__device__ float  d_b1x[NEXPX * DFF];
__device__ float  d_b2x[NEXPX * DMODEL];
__device__ __half d_xh[(size_t)NTOK * DMODEL];
__device__ __half d_Hh[(size_t)NROWS * DFF];
__device__ float  d_ybuf[(size_t)NROWS * DMODEL];
__device__ float  d_gates[NASSIGN];
__device__ int    d_assign_e[NASSIGN];
__device__ int    d_offsets[NEXPX + 1];
__device__ int    d_rows_token[NROWS];
__device__ int    d_rowof[NASSIGN];

// ---------------- helpers --------------------------------------------------------------
__device__ __forceinline__ float gelu_tanh(float v) {
    const float c0 = 0.7978845608028654f;
    const float c1 = 0.044715f;
    float t = tanhf(c0 * (v + c1 * v * v * v));
    return 0.5f * v * (1.0f + t);
}

__device__ __forceinline__ void mma16816(float* c, const uint32_t* a, const uint32_t* b) {
    asm volatile(
        "mma.sync.aligned.m16n8k16.row.col.f32.f16.f16.f32 "
        "{%0,%1,%2,%3}, {%4,%5,%6,%7}, {%8,%9}, {%0,%1,%2,%3};"
        : "+f"(c[0]), "+f"(c[1]), "+f"(c[2]), "+f"(c[3])
        : "r"(a[0]), "r"(a[1]), "r"(a[2]), "r"(a[3]), "r"(b[0]), "r"(b[1]));
}

__device__ __forceinline__ void ldsm4(uint32_t* r, uint32_t addr) {
    asm volatile("ldmatrix.sync.aligned.m8n8.x4.shared.b16 {%0,%1,%2,%3}, [%4];"
                 : "=r"(r[0]), "=r"(r[1]), "=r"(r[2]), "=r"(r[3]) : "r"(addr));
}

__device__ __forceinline__ uint32_t smem_u32(const void* p) {
    uint32_t a;
    asm("{ .reg .u64 t; cvta.to.shared.u64 t, %1; cvt.u32.u64 %0, t; }" : "=r"(a) : "l"(p));
    return a;
}

__device__ __forceinline__ void cp16(uint32_t saddr, const void* g, int srcsz) {
    asm volatile("cp.async.cg.shared.global [%0], [%1], 16, %2;"
                 :: "r"(saddr), "l"(g), "r"(srcsz) : "memory");
}
#define CP_COMMIT() asm volatile("cp.async.commit_group;" ::: "memory")
#define CP_WAIT1()  asm volatile("cp.async.wait_group 1;" ::: "memory")

// ---------------- launch 1: router -------------------------------------------------------
__global__ void router_kernel(const float* __restrict__ x,
                              const float* __restrict__ wr) {
    int t = blockIdx.x;
    int warp = threadIdx.x >> 5;
    int lane = threadIdx.x & 31;
    const float* xr = x + (size_t)t * DMODEL;
    const float* w  = wr + (size_t)warp * DMODEL;
    float s = 0.f;
    #pragma unroll 4
    for (int i = lane; i < DMODEL; i += 32) s += xr[i] * w[i];
    #pragma unroll
    for (int o = 16; o > 0; o >>= 1) s += __shfl_xor_sync(0xFFFFFFFFu, s, o);

    __shared__ float logits[NEXP];
    if (lane == 0) logits[warp] = s;
    __syncthreads();

    if (threadIdx.x == 0) {
        float mx = logits[0];
        #pragma unroll
        for (int e = 1; e < NEXP; e++) mx = fmaxf(mx, logits[e]);
        float p[NEXP]; float sum = 0.f;
        #pragma unroll
        for (int e = 0; e < NEXP; e++) { p[e] = expf(logits[e] - mx); sum += p[e]; }
        float inv = 1.f / sum;
        #pragma unroll
        for (int e = 0; e < NEXP; e++) p[e] *= inv;
        int i0 = 0;
        #pragma unroll
        for (int e = 1; e < NEXP; e++) if (p[e] > p[i0]) i0 = e;
        int i1 = -1;
        #pragma unroll
        for (int e = 0; e < NEXP; e++) {
            if (e == i0) continue;
            if (i1 < 0 || p[e] > p[i1]) i1 = e;
        }
        d_gates[2 * t + 0] = p[i0];
        d_gates[2 * t + 1] = p[i1];
        d_assign_e[2 * t + 0] = i0;
        d_assign_e[2 * t + 1] = i1;
    }
}

// ---------------- launch 2: single-block count + scan + place ----------------------------
__global__ void scanplace_kernel() {
    __shared__ int scount[NEXP];
    __shared__ int scursor[NEXP];
    int tid = threadIdx.x;
    if (tid < NEXP) scount[tid] = 0;
    __syncthreads();
    for (int a = tid; a < NASSIGN; a += blockDim.x)
        atomicAdd(&scount[d_assign_e[a]], 1);
    __syncthreads();
    if (tid == 0) {
        int s = 0;
        for (int e = 0; e < NEXP; e++) { d_offsets[e] = s; scursor[e] = s; s += scount[e]; }
        d_offsets[NEXP]  = s;
        d_offsets[NEXPX] = NROWS;
    }
    __syncthreads();
    for (int a = tid; a < NASSIGN; a += blockDim.x) {
        int e = d_assign_e[a];
        int r = atomicAdd(&scursor[e], 1);
        d_rows_token[r] = a >> 1;
        d_rowof[a] = r;
    }
    for (int t = tid; t < NTOK; t += blockDim.x)
        d_rows_token[NASSIGN + t] = t;
}

// ---------------- launch 3: x -> fp16 + bias packing --------------------------------------
__global__ void cvt_x_bias(const float4* __restrict__ x,
                           uint2* __restrict__ xh,
                           const float* __restrict__ b1, const float* __restrict__ bs1,
                           const float* __restrict__ b2, const float* __restrict__ bs2,
                           float* __restrict__ b1x, float* __restrict__ b2x) {
    const int n4 = NTOK * DMODEL / 4;
    for (int i = blockIdx.x * blockDim.x + threadIdx.x; i < n4; i += gridDim.x * blockDim.x) {
        float4 v = x[i];
        __half2 a = __floats2half2_rn(v.x, v.y);
        __half2 b = __floats2half2_rn(v.z, v.w);
        xh[i] = make_uint2(*(uint32_t*)&a, *(uint32_t*)&b);
    }
    for (int i = blockIdx.x * blockDim.x + threadIdx.x; i < NEXPX * DFF; i += gridDim.x * blockDim.x)
        b1x[i] = (i < NEXP * DFF) ? b1[i] : bs1[i - NEXP * DFF];
    for (int i = blockIdx.x * blockDim.x + threadIdx.x; i < NEXPX * DMODEL; i += gridDim.x * blockDim.x)
        b2x[i] = (i < NEXP * DMODEL) ? b2[i] : bs2[i - NEXP * DMODEL];
}

// ---------------- launches 4 & 6: weights -> 9-expert fp16 buffer --------------------------
__global__ void cvt_w9(const float4* __restrict__ w8, const float4* __restrict__ ws,
                       uint2* __restrict__ dst, int n4_routed, int n4_total) {
    for (int i = blockIdx.x * blockDim.x + threadIdx.x; i < n4_total; i += gridDim.x * blockDim.x) {
        float4 v = (i < n4_routed) ? w8[i] : ws[i - n4_routed];
        __half2 a = __floats2half2_rn(v.x, v.y);
        __half2 b = __floats2half2_rn(v.z, v.w);
        dst[i] = make_uint2(*(uint32_t*)&a, *(uint32_t*)&b);
    }
}

// ================= fp16 HMMA grouped GEMM, cp.async 3-stage, BK=64 =======================
// 128x128x64 CTA tile, 256 thr (8 warps 2x4), m16n8k16, 3-stage LDGSTS pipeline.
// SMEM stage: A@0 (128 rows x 144B), B@18432; stage = 36864 B; 3 stages = 110592 B.
#define RS      144
#define T_B     18432
#define STAGE_B 36864
#define NSTAGE  3
#define GEMM_SMEM (NSTAGE * STAGE_B)

__global__ __launch_bounds__(256, 2)
void gemm_tc(const __half* __restrict__ Ah, int lda, const int* __restrict__ gather,
             const __half* __restrict__ Bh_base, size_t wstride,
             const float* __restrict__ bias_base, size_t bstride,
             float* __restrict__ Cf, __half* __restrict__ Ch, int ldc,
             const int* __restrict__ offs, int K, int do_gelu)
{
    extern __shared__ char smem[];
    int e  = blockIdx.z;
    int lo = offs[e];
    int hi = offs[e + 1];
    int m0 = lo + blockIdx.y * 128;
    if (m0 >= hi) return;
    int n0 = blockIdx.x * 128;
    const __half* Bh = Bh_base + (size_t)e * wstride;
    const float* bias = bias_base + (size_t)e * bstride;

    uint32_t sbase = smem_u32(smem);
    int tid  = threadIdx.x;
    int wid  = tid >> 5;
    int lane = tid & 31;
    int tig  = lane & 3;
    int wm   = wid >> 2;
    int wn   = wid & 3;

    // ---- cp.async coords: thread owns row tid>>1, 64B half-row (4 x 16B) ------------
    int r    = tid >> 1;             // 0..127
    int cb   = (tid & 1) * 64;       // byte base within 128B row: 0 or 64
    int arow = m0 + r;
    int av16 = (arow < hi) ? 16 : 0; // cp.async src-size predicate
    int asrc = (arow < hi) ? (gather ? gather[arow] : arow) : 0;
    const char* gA = (const char*)(Ah + (size_t)asrc * lda) + cb;
    const char* gB = (const char*)(Bh + (size_t)(n0 + r) * K) + cb;
    uint32_t sA = sbase + (uint32_t)(r * RS + cb);
    uint32_t sB = sbase + (uint32_t)(T_B + r * RS + cb);

    // ---- ldmatrix lane offsets --------------------------------------------------------
    uint32_t aoff[4], boff[4];
    #pragma unroll
    for (int mi = 0; mi < 4; mi++)
        aoff[mi] = (uint32_t)((wm * 64 + mi * 16 + (lane & 15)) * RS + (lane >> 4) * 16);
    #pragma unroll
    for (int ni = 0; ni < 4; ni++)
        boff[ni] = (uint32_t)(T_B + (wn * 32 + ni * 8 + (lane & 7)) * RS + (lane >> 3) * 16);

    float acc[4][4][4];
    #pragma unroll
    for (int mi = 0; mi < 4; mi++)
        #pragma unroll
        for (int ni = 0; ni < 4; ni++)
            #pragma unroll
            for (int q = 0; q < 4; q++) acc[mi][ni][q] = 0.f;

    int nk = K >> 6;   // K/64

    // issue loads for a stage: 4x16B A + 4x16B B per thread (stage KB bytes = 128 halves)
    auto issue = [&](int kt, int s) {
        uint32_t so = (uint32_t)(s * STAGE_B);
        int kbyte = kt << 7;           // kt*128 bytes (64 halves)
        #pragma unroll
        for (int j = 0; j < 4; j++) {
            cp16(sA + so + j * 16, gA + kbyte + j * 16, av16);
            cp16(sB + so + j * 16, gB + kbyte + j * 16, 16);
        }
        CP_COMMIT();
    };

    // prologue: stages 0,1
    issue(0, 0);
    if (nk > 1) issue(1, 1); else CP_COMMIT();

    int s = 0;
    for (int kt = 0; kt < nk; kt++) {
        CP_WAIT1();
        __syncthreads();

        // issue next-next stage before compute
        if (kt + 2 < nk) issue(kt + 2, (s + 2) % NSTAGE);
        else CP_COMMIT();   // keep group counting uniform

        uint32_t st = sbase + (uint32_t)(s * STAGE_B);

        uint32_t bhf[4][4];
        #pragma unroll
        for (int ks = 0; ks < 4; ks++) {
            if ((ks & 1) == 0) {
                #pragma unroll
                for (int ni = 0; ni < 4; ni++)
                    ldsm4(bhf[ni], st + boff[ni] + (ks >> 1) * 64);
            }
            uint32_t ahf[4][4];
            #pragma unroll
            for (int mi = 0; mi < 4; mi++)
                ldsm4(ahf[mi], st + aoff[mi] + ks * 32);
            #pragma unroll
            for (int mi = 0; mi < 4; mi++)
                #pragma unroll
                for (int ni = 0; ni < 4; ni++)
                    mma16816(acc[mi][ni], ahf[mi], &bhf[ni][2 * (ks & 1)]);
        }

        s = (s + 1) % NSTAGE;
    }

    // ---------------- epilogue ------------------------------------------------------------
    int g = lane >> 2;
    #pragma unroll
    for (int mi = 0; mi < 4; mi++) {
        int row0 = m0 + wm * 64 + mi * 16 + g;
        int row1 = row0 + 8;
        #pragma unroll
        for (int ni = 0; ni < 4; ni++) {
            int cn = n0 + wn * 32 + ni * 8 + tig * 2;
            float b0 = bias[cn], b1 = bias[cn + 1];
            #pragma unroll
            for (int h = 0; h < 2; h++) {
                int row = h ? row1 : row0;
                if (row >= hi) continue;
                float v0 = acc[mi][ni][2 * h + 0] + b0;
                float v1 = acc[mi][ni][2 * h + 1] + b1;
                if (do_gelu) { v0 = gelu_tanh(v0); v1 = gelu_tanh(v1); }
                if (Ch) {
                    __half2 hp = __floats2half2_rn(v0, v1);
                    *(uint32_t*)(Ch + (size_t)row * ldc + cn) = *(uint32_t*)&hp;
                } else {
                    *(float2*)(Cf + (size_t)row * ldc + cn) = make_float2(v0, v1);
                }
            }
        }
    }
}

// ---------------- launch 8: combine --------------------------------------------------------
__global__ void combine_kernel(float* __restrict__ out) {
    int t = blockIdx.x;
    float g0 = d_gates[2 * t + 0];
    float g1 = d_gates[2 * t + 1];
    const float* y0 = d_ybuf + (size_t)d_rowof[2 * t + 0] * DMODEL;
    const float* y1 = d_ybuf + (size_t)d_rowof[2 * t + 1] * DMODEL;
    const float* ys = d_ybuf + (size_t)(NASSIGN + t) * DMODEL;
    float* o = out + (size_t)t * DMODEL;
    for (int d = threadIdx.x * 4; d < DMODEL; d += blockDim.x * 4) {
        float4 sv = *(const float4*)(ys + d);
        float4 a  = *(const float4*)(y0 + d);
        float4 b  = *(const float4*)(y1 + d);
        float4 ov;
        ov.x = SCALE_F * (sv.x + g0 * a.x + g1 * b.x);
        ov.y = SCALE_F * (sv.y + g0 * a.y + g1 * b.y);
        ov.z = SCALE_F * (sv.z + g0 * a.z + g1 * b.z);
        ov.w = SCALE_F * (sv.w + g0 * a.w + g1 * b.w);
        *(float4*)(o + d) = ov;
    }
}

// ---------------- launcher --------------------------------------------------------------------
extern "C" void kernel_launch(void* const* d_in, const int* in_sizes, int n_in,
                              void* d_out, int out_size)
{
    const float* x   = (const float*)d_in[0];
    const float* wr  = (const float*)d_in[1];
    const float* W1  = (const float*)d_in[2];
    const float* b1  = (const float*)d_in[3];
    const float* W2  = (const float*)d_in[4];
    const float* b2  = (const float*)d_in[5];
    const float* Ws1 = (const float*)d_in[6];
    const float* bs1 = (const float*)d_in[7];
    const float* Ws2 = (const float*)d_in[8];
    const float* bs2 = (const float*)d_in[9];
    float* out = (float*)d_out;

    __half *W1x, *W2x, *xh, *Hh;
    float *ybuf, *b1x, *b2x;
    int *offsets, *rows_token;
    cudaGetSymbolAddress((void**)&W1x, d_W1x);
    cudaGetSymbolAddress((void**)&W2x, d_W2x);
    cudaGetSymbolAddress((void**)&b1x, d_b1x);
    cudaGetSymbolAddress((void**)&b2x, d_b2x);
    cudaGetSymbolAddress((void**)&xh, d_xh);
    cudaGetSymbolAddress((void**)&Hh, d_Hh);
    cudaGetSymbolAddress((void**)&ybuf, d_ybuf);
    cudaGetSymbolAddress((void**)&offsets, d_offsets);
    cudaGetSymbolAddress((void**)&rows_token, d_rows_token);

    cudaFuncSetAttribute(gemm_tc, cudaFuncAttributeMaxDynamicSharedMemorySize, GEMM_SMEM);

    // 1-2) routing
    router_kernel<<<NTOK, 256>>>(x, wr);
    scanplace_kernel<<<1, 1024>>>();

    // 3) x conversion + bias packing
    cvt_x_bias<<<2048, 256>>>((const float4*)x, (uint2*)xh, b1, bs1, b2, bs2, b1x, b2x);

    // 4) up-weights -> 9-expert fp16
    cvt_w9<<<8192, 256>>>((const float4*)W1, (const float4*)Ws1, (uint2*)W1x,
                          NEXP * DFF * DMODEL / 4, NEXPX * DFF * DMODEL / 4);

    // 5) unified up-GEMM (ncu -s 5 -c 1 lands here)
    {
        dim3 g(DFF / 128, 32, NEXPX);
        gemm_tc<<<g, 256, GEMM_SMEM>>>(xh, DMODEL, rows_token,
                                       W1x, (size_t)DFF * DMODEL, b1x, DFF,
                                       nullptr, Hh, DFF,
                                       offsets, DMODEL, 1);
    }

    // 6) down-weights -> 9-expert fp16
    cvt_w9<<<8192, 256>>>((const float4*)W2, (const float4*)Ws2, (uint2*)W2x,
                          NEXP * DMODEL * DFF / 4, NEXPX * DMODEL * DFF / 4);

    // 7) unified down-GEMM
    {
        dim3 g(DMODEL / 128, 32, NEXPX);
        gemm_tc<<<g, 256, GEMM_SMEM>>>(Hh, DFF, nullptr,
                                       W2x, (size_t)DMODEL * DFF, b2x, DMODEL,
                                       ybuf, nullptr, DMODEL,
                                       offsets, DFF, 0);
    }

    // 8) combine
    combine_kernel<<<NTOK, 256>>>(out);
}

// round 10
// speedup vs baseline: 5.0976x; 1.0180x over previous
#include <cuda_runtime.h>
#include <cuda_fp16.h>
#include <stdint.h>
#include <math.h>

#define NTOK   4096
#define DMODEL 1024
#define DFF    4096
#define NEXP   8
#define NEXPX  9                 // 8 routed + 1 shared
#define NASSIGN (NTOK*2)
#define NROWS  (NASSIGN + NTOK)  // 12288 unified rows
#define SCALE_F 0.894427190999915878f

// ---------------- device scratch ----------------------------------------------------
__device__ __half d_W1x[(size_t)NEXPX * DFF * DMODEL];
__device__ __half d_W2x[(size_t)NEXPX * DMODEL * DFF];
__device__ float  d_b1x[NEXPX * DFF];
__device__ float  d_b2x[NEXPX * DMODEL];
__device__ __half d_xh[(size_t)NTOK * DMODEL];
__device__ __half d_Hh[(size_t)NROWS * DFF];
__device__ float  d_gates[NASSIGN];
__device__ int    d_assign_e[NASSIGN];
__device__ int    d_offsets[NEXPX + 1];
__device__ int    d_rows_token[NROWS];    // GEMM row -> token
__device__ float  d_growsc[NROWS];        // GEMM row -> SCALE*gate (routed) / SCALE (shared)

// ---------------- helpers --------------------------------------------------------------
__device__ __forceinline__ float gelu_tanh(float v) {
    const float c0 = 0.7978845608028654f;
    const float c1 = 0.044715f;
    float t = tanhf(c0 * (v + c1 * v * v * v));
    return 0.5f * v * (1.0f + t);
}

__device__ __forceinline__ void mma16816(float* c, const uint32_t* a, const uint32_t* b) {
    asm volatile(
        "mma.sync.aligned.m16n8k16.row.col.f32.f16.f16.f32 "
        "{%0,%1,%2,%3}, {%4,%5,%6,%7}, {%8,%9}, {%0,%1,%2,%3};"
        : "+f"(c[0]), "+f"(c[1]), "+f"(c[2]), "+f"(c[3])
        : "r"(a[0]), "r"(a[1]), "r"(a[2]), "r"(a[3]), "r"(b[0]), "r"(b[1]));
}

__device__ __forceinline__ void ldsm4(uint32_t* r, uint32_t addr) {
    asm volatile("ldmatrix.sync.aligned.m8n8.x4.shared.b16 {%0,%1,%2,%3}, [%4];"
                 : "=r"(r[0]), "=r"(r[1]), "=r"(r[2]), "=r"(r[3]) : "r"(addr));
}

__device__ __forceinline__ uint32_t smem_u32(const void* p) {
    uint32_t a;
    asm("{ .reg .u64 t; cvta.to.shared.u64 t, %1; cvt.u32.u64 %0, t; }" : "=r"(a) : "l"(p));
    return a;
}

__device__ __forceinline__ void cp16(uint32_t saddr, const void* g, int srcsz) {
    asm volatile("cp.async.cg.shared.global [%0], [%1], 16, %2;"
                 :: "r"(saddr), "l"(g), "r"(srcsz) : "memory");
}
#define CP_COMMIT() asm volatile("cp.async.commit_group;" ::: "memory")
#define CP_WAIT1()  asm volatile("cp.async.wait_group 1;" ::: "memory")

__device__ __forceinline__ void cvt_store(const float4* __restrict__ src, uint2* __restrict__ dst, int i) {
    float4 v = src[i];
    __half2 a = __floats2half2_rn(v.x, v.y);
    __half2 b = __floats2half2_rn(v.z, v.w);
    dst[i] = make_uint2(*(uint32_t*)&a, *(uint32_t*)&b);
}

// ---------------- launch 1: router + W1/x/bias conversion (fused) -------------------------
#define CVT_BLOCKS 4096
__global__ void router_cvt(const float* __restrict__ x,
                           const float* __restrict__ wr,
                           const float4* __restrict__ W1, const float4* __restrict__ Ws1,
                           const float* __restrict__ b1, const float* __restrict__ bs1,
                           const float* __restrict__ b2, const float* __restrict__ bs2,
                           uint2* __restrict__ W1x, uint2* __restrict__ xh,
                           float* __restrict__ b1x, float* __restrict__ b2x) {
    if (blockIdx.x >= NTOK) {
        // ---- conversion path (4096 CTAs, overlaps routing) ----
        int idx0 = (blockIdx.x - NTOK) * blockDim.x + threadIdx.x;
        const int nthr = CVT_BLOCKS * 256;
        const int n4r = NEXP * DFF * DMODEL / 4;
        const int n4t = NEXPX * DFF * DMODEL / 4;
        for (int i = idx0; i < n4t; i += nthr) {
            float4 v = (i < n4r) ? W1[i] : Ws1[i - n4r];
            __half2 a = __floats2half2_rn(v.x, v.y);
            __half2 b = __floats2half2_rn(v.z, v.w);
            W1x[i] = make_uint2(*(uint32_t*)&a, *(uint32_t*)&b);
        }
        for (int i = idx0; i < NTOK * DMODEL / 4; i += nthr)
            cvt_store((const float4*)x, xh, i);
        for (int i = idx0; i < NEXPX * DFF; i += nthr)
            b1x[i] = (i < NEXP * DFF) ? b1[i] : bs1[i - NEXP * DFF];
        for (int i = idx0; i < NEXPX * DMODEL; i += nthr)
            b2x[i] = (i < NEXP * DMODEL) ? b2[i] : bs2[i - NEXP * DMODEL];
        return;
    }
    // ---- routing path ----
    int t = blockIdx.x;
    int warp = threadIdx.x >> 5;
    int lane = threadIdx.x & 31;
    const float* xr = x + (size_t)t * DMODEL;
    const float* w  = wr + (size_t)warp * DMODEL;
    float s = 0.f;
    #pragma unroll 4
    for (int i = lane; i < DMODEL; i += 32) s += xr[i] * w[i];
    #pragma unroll
    for (int o = 16; o > 0; o >>= 1) s += __shfl_xor_sync(0xFFFFFFFFu, s, o);

    __shared__ float logits[NEXP];
    if (warp < NEXP && lane == 0) logits[warp] = s;
    __syncthreads();

    if (threadIdx.x == 0) {
        float mx = logits[0];
        #pragma unroll
        for (int e = 1; e < NEXP; e++) mx = fmaxf(mx, logits[e]);
        float p[NEXP]; float sum = 0.f;
        #pragma unroll
        for (int e = 0; e < NEXP; e++) { p[e] = expf(logits[e] - mx); sum += p[e]; }
        float inv = 1.f / sum;
        #pragma unroll
        for (int e = 0; e < NEXP; e++) p[e] *= inv;
        int i0 = 0;
        #pragma unroll
        for (int e = 1; e < NEXP; e++) if (p[e] > p[i0]) i0 = e;
        int i1 = -1;
        #pragma unroll
        for (int e = 0; e < NEXP; e++) {
            if (e == i0) continue;
            if (i1 < 0 || p[e] > p[i1]) i1 = e;
        }
        d_gates[2 * t + 0] = p[i0];
        d_gates[2 * t + 1] = p[i1];
        d_assign_e[2 * t + 0] = i0;
        d_assign_e[2 * t + 1] = i1;
    }
}

// ---------------- launch 2: single-block count + scan + place ----------------------------
__global__ void scanplace_kernel() {
    __shared__ int scount[NEXP];
    __shared__ int scursor[NEXP];
    int tid = threadIdx.x;
    if (tid < NEXP) scount[tid] = 0;
    __syncthreads();
    for (int a = tid; a < NASSIGN; a += blockDim.x)
        atomicAdd(&scount[d_assign_e[a]], 1);
    __syncthreads();
    if (tid == 0) {
        int s = 0;
        for (int e = 0; e < NEXP; e++) { d_offsets[e] = s; scursor[e] = s; s += scount[e]; }
        d_offsets[NEXP]  = s;
        d_offsets[NEXPX] = NROWS;
    }
    __syncthreads();
    for (int a = tid; a < NASSIGN; a += blockDim.x) {
        int e = d_assign_e[a];
        int r = atomicAdd(&scursor[e], 1);
        d_rows_token[r] = a >> 1;
        d_growsc[r] = SCALE_F * d_gates[a];
    }
    for (int t = tid; t < NTOK; t += blockDim.x) {
        d_rows_token[NASSIGN + t] = t;
        d_growsc[NASSIGN + t] = SCALE_F;
    }
}

// ================= fp16 HMMA grouped GEMM, cp.async 3-stage, BK=64 =======================
// 128x128x64 CTA tile, 256 thr (8 warps 2x4), m16n8k16, 3-stage LDGSTS pipeline.
// z = e*kh_count + kh (K split). z >= 9*kh_count -> weight-conversion CTAs (up-GEMM only).
// Epilogue: Ch!=null -> fp16+gelu store (up). Else atomicAdd gate-scaled into out (down).
#define RS      144
#define T_B     18432
#define STAGE_B 36864
#define NSTAGE  3
#define GEMM_SMEM (NSTAGE * STAGE_B)

__global__ __launch_bounds__(256, 2)
void gemm_tc(const __half* __restrict__ Ah, int lda, const int* __restrict__ gather,
             const __half* __restrict__ Bh_base, size_t wstride,
             const float* __restrict__ bias_base, size_t bstride,
             __half* __restrict__ Ch, int ldc,
             float* __restrict__ out_at,
             const int* __restrict__ rows_token, const float* __restrict__ growsc,
             const int* __restrict__ offs, int K, int kh_count, int do_gelu,
             const float4* __restrict__ cw8, const float4* __restrict__ cws,
             uint2* __restrict__ cdst, int cn4r, int cn4t)
{
    extern __shared__ char smem[];
    int z = blockIdx.z;
    int nz_gemm = NEXPX * kh_count;
    if (z >= nz_gemm) {
        // ---- fused weight conversion (runs in the GEMM's tail waves) ----
        int idx0 = (blockIdx.y * gridDim.x + blockIdx.x) * blockDim.x + threadIdx.x;
        int nthr = gridDim.x * gridDim.y * blockDim.x;
        for (int i = idx0; i < cn4t; i += nthr) {
            float4 v = (i < cn4r) ? cw8[i] : cws[i - cn4r];
            __half2 a = __floats2half2_rn(v.x, v.y);
            __half2 b = __floats2half2_rn(v.z, v.w);
            cdst[i] = make_uint2(*(uint32_t*)&a, *(uint32_t*)&b);
        }
        return;
    }
    int e  = z / kh_count;
    int kh = z - e * kh_count;
    int Ks = K / kh_count;
    int lo = offs[e];
    int hi = offs[e + 1];
    int m0 = lo + blockIdx.y * 128;
    if (m0 >= hi) return;
    int n0 = blockIdx.x * 128;
    const __half* Bh = Bh_base + (size_t)e * wstride + kh * Ks;
    const float* bias = bias_base + (size_t)e * bstride;

    uint32_t sbase = smem_u32(smem);
    int tid  = threadIdx.x;
    int wid  = tid >> 5;
    int lane = tid & 31;
    int tig  = lane & 3;
    int wm   = wid >> 2;
    int wn   = wid & 3;

    int r    = tid >> 1;
    int cb   = (tid & 1) * 64;
    int arow = m0 + r;
    int av16 = (arow < hi) ? 16 : 0;
    int asrc = (arow < hi) ? (gather ? gather[arow] : arow) : 0;
    const char* gA = (const char*)(Ah + (size_t)asrc * lda + kh * Ks) + cb;
    const char* gB = (const char*)(Bh + (size_t)(n0 + r) * K) + cb;
    uint32_t sA = sbase + (uint32_t)(r * RS + cb);
    uint32_t sB = sbase + (uint32_t)(T_B + r * RS + cb);

    uint32_t aoff[4], boff[4];
    #pragma unroll
    for (int mi = 0; mi < 4; mi++)
        aoff[mi] = (uint32_t)((wm * 64 + mi * 16 + (lane & 15)) * RS + (lane >> 4) * 16);
    #pragma unroll
    for (int ni = 0; ni < 4; ni++)
        boff[ni] = (uint32_t)(T_B + (wn * 32 + ni * 8 + (lane & 7)) * RS + (lane >> 3) * 16);

    float acc[4][4][4];
    #pragma unroll
    for (int mi = 0; mi < 4; mi++)
        #pragma unroll
        for (int ni = 0; ni < 4; ni++)
            #pragma unroll
            for (int q = 0; q < 4; q++) acc[mi][ni][q] = 0.f;

    int nk = Ks >> 6;

    auto issue = [&](int kt, int s) {
        uint32_t so = (uint32_t)(s * STAGE_B);
        int kbyte = kt << 7;
        #pragma unroll
        for (int j = 0; j < 4; j++) {
            cp16(sA + so + j * 16, gA + kbyte + j * 16, av16);
            cp16(sB + so + j * 16, gB + kbyte + j * 16, 16);
        }
        CP_COMMIT();
    };

    issue(0, 0);
    if (nk > 1) issue(1, 1); else CP_COMMIT();

    int s = 0;
    for (int kt = 0; kt < nk; kt++) {
        CP_WAIT1();
        __syncthreads();

        if (kt + 2 < nk) issue(kt + 2, (s + 2) % NSTAGE);
        else CP_COMMIT();

        uint32_t st = sbase + (uint32_t)(s * STAGE_B);

        uint32_t bhf[4][4];
        #pragma unroll
        for (int ks = 0; ks < 4; ks++) {
            if ((ks & 1) == 0) {
                #pragma unroll
                for (int ni = 0; ni < 4; ni++)
                    ldsm4(bhf[ni], st + boff[ni] + (ks >> 1) * 64);
            }
            uint32_t ahf[4][4];
            #pragma unroll
            for (int mi = 0; mi < 4; mi++)
                ldsm4(ahf[mi], st + aoff[mi] + ks * 32);
            #pragma unroll
            for (int mi = 0; mi < 4; mi++)
                #pragma unroll
                for (int ni = 0; ni < 4; ni++)
                    mma16816(acc[mi][ni], ahf[mi], &bhf[ni][2 * (ks & 1)]);
        }

        s = (s + 1) % NSTAGE;
    }

    // ---------------- epilogue ------------------------------------------------------------
    int g = lane >> 2;
    #pragma unroll
    for (int mi = 0; mi < 4; mi++) {
        int row0 = m0 + wm * 64 + mi * 16 + g;
        #pragma unroll
        for (int h = 0; h < 2; h++) {
            int row = row0 + h * 8;
            if (row >= hi) continue;
            if (Ch) {
                #pragma unroll
                for (int ni = 0; ni < 4; ni++) {
                    int cn = n0 + wn * 32 + ni * 8 + tig * 2;
                    float v0 = acc[mi][ni][2 * h + 0] + bias[cn];
                    float v1 = acc[mi][ni][2 * h + 1] + bias[cn + 1];
                    if (do_gelu) { v0 = gelu_tanh(v0); v1 = gelu_tanh(v1); }
                    __half2 hp = __floats2half2_rn(v0, v1);
                    *(uint32_t*)(Ch + (size_t)row * ldc + cn) = *(uint32_t*)&hp;
                }
            } else {
                int tok = rows_token[row];
                float gs = growsc[row];
                float* ob = out_at + (size_t)tok * DMODEL;
                #pragma unroll
                for (int ni = 0; ni < 4; ni++) {
                    int cn = n0 + wn * 32 + ni * 8 + tig * 2;
                    float b0 = (kh == 0) ? bias[cn]     : 0.f;
                    float b1 = (kh == 0) ? bias[cn + 1] : 0.f;
                    atomicAdd(ob + cn,     gs * (acc[mi][ni][2 * h + 0] + b0));
                    atomicAdd(ob + cn + 1, gs * (acc[mi][ni][2 * h + 1] + b1));
                }
            }
        }
    }
}

// ---------------- launcher --------------------------------------------------------------------
extern "C" void kernel_launch(void* const* d_in, const int* in_sizes, int n_in,
                              void* d_out, int out_size)
{
    const float* x   = (const float*)d_in[0];
    const float* wr  = (const float*)d_in[1];
    const float* W1  = (const float*)d_in[2];
    const float* b1  = (const float*)d_in[3];
    const float* W2  = (const float*)d_in[4];
    const float* b2  = (const float*)d_in[5];
    const float* Ws1 = (const float*)d_in[6];
    const float* bs1 = (const float*)d_in[7];
    const float* Ws2 = (const float*)d_in[8];
    const float* bs2 = (const float*)d_in[9];
    float* out = (float*)d_out;

    __half *W1x, *W2x, *xh, *Hh;
    float *b1x, *b2x, *growsc;
    int *offsets, *rows_token;
    cudaGetSymbolAddress((void**)&W1x, d_W1x);
    cudaGetSymbolAddress((void**)&W2x, d_W2x);
    cudaGetSymbolAddress((void**)&b1x, d_b1x);
    cudaGetSymbolAddress((void**)&b2x, d_b2x);
    cudaGetSymbolAddress((void**)&xh, d_xh);
    cudaGetSymbolAddress((void**)&Hh, d_Hh);
    cudaGetSymbolAddress((void**)&growsc, d_growsc);
    cudaGetSymbolAddress((void**)&offsets, d_offsets);
    cudaGetSymbolAddress((void**)&rows_token, d_rows_token);

    cudaFuncSetAttribute(gemm_tc, cudaFuncAttributeMaxDynamicSharedMemorySize, GEMM_SMEM);

    // 1) router + W1/x/bias conversion (fused, overlapped)
    router_cvt<<<NTOK + CVT_BLOCKS, 256>>>(x, wr,
                                           (const float4*)W1, (const float4*)Ws1,
                                           b1, bs1, b2, bs2,
                                           (uint2*)W1x, (uint2*)xh, b1x, b2x);

    // 2) scan + place + gate-scale table
    scanplace_kernel<<<1, 1024>>>();

    // 3) zero output (down-GEMM accumulates atomically)
    cudaMemsetAsync(out, 0, (size_t)NTOK * DMODEL * sizeof(float));

    // 4) up-GEMM (z=0..8) + fused W2 conversion (z=9, fills tail waves)
    {
        dim3 g(DFF / 128, 32, NEXPX + 1);
        gemm_tc<<<g, 256, GEMM_SMEM>>>(xh, DMODEL, rows_token,
                                       W1x, (size_t)DFF * DMODEL, b1x, DFF,
                                       Hh, DFF,
                                       nullptr, nullptr, nullptr,
                                       offsets, DMODEL, 1, 1,
                                       (const float4*)W2, (const float4*)Ws2, (uint2*)W2x,
                                       NEXP * DMODEL * DFF / 4, NEXPX * DMODEL * DFF / 4);
    }

    // 5) down-GEMM, split-K=2, gate-scaled atomic accumulate into out
    {
        dim3 g(DMODEL / 128, 32, NEXPX * 2);
        gemm_tc<<<g, 256, GEMM_SMEM>>>(Hh, DFF, nullptr,
                                       W2x, (size_t)DMODEL * DFF, b2x, DMODEL,
                                       nullptr, 0,
                                       out, rows_token, growsc,
                                       offsets, DFF, 2, 0,
                                       nullptr, nullptr, nullptr, 0, 0);
    }
}